// round 8
// baseline (speedup 1.0000x reference)
#include <cuda_runtime.h>
#include <math.h>

// Problem constants
#define BB 256
#define PP 5
#define TT 256
#define FF 128
#define HH 512
#define CC 60
#define DD 640      // P*F
#define G4 2048     // 4*H

// Scratch state (device globals: allocation-free per harness rules)
__device__ float g_xw[134217728ULL];   // (T*B, 4H) = 65536 x 2048 fp32
__device__ float g_h[2][BB * HH];      // double-buffered hidden state
__device__ unsigned g_bar4[4];         // per-row-group barrier counters

// ---------------------------------------------------------------------------
// Packed fp32x2 FMA (SASS FFMA2)
// ---------------------------------------------------------------------------
__device__ __forceinline__ float2 ffma2(float2 a, float2 b, float2 c) {
    unsigned long long ua = *reinterpret_cast<unsigned long long*>(&a);
    unsigned long long ub = *reinterpret_cast<unsigned long long*>(&b);
    unsigned long long uc = *reinterpret_cast<unsigned long long*>(&c);
    unsigned long long ud;
    asm("fma.rn.f32x2 %0, %1, %2, %3;" : "=l"(ud) : "l"(ua), "l"(ub), "l"(uc));
    return *reinterpret_cast<float2*>(&ud);
}

// ---------------------------------------------------------------------------
// Zero initial state + reset barriers (runs every launch)
// ---------------------------------------------------------------------------
__global__ void zero_state() {
    int i = blockIdx.x * blockDim.x + threadIdx.x;
    if (i < BB * HH) g_h[0][i] = 0.0f;
    if (i < 4) g_bar4[i] = 0u;
}

// ---------------------------------------------------------------------------
// Phase 1: XW[t*B+b, :] = x_seq[t,b,:] @ Wx + bias  (unchanged — near peak)
// ---------------------------------------------------------------------------
#define KT1 16
__global__ void __launch_bounds__(256, 2)
xw_gemm(const float* __restrict__ X, const float* __restrict__ Wx,
        const float* __restrict__ bvec) {
    __shared__ float a_s[2][KT1][130];
    __shared__ float b_s[2][KT1][128];

    const int tid = threadIdx.x;
    const int by  = blockIdx.y;
    const int n0  = blockIdx.x << 7;
    const int t   = by >> 1;
    const int bb0 = (by & 1) << 7;

    const int tx = tid & 15;
    const int ty = tid >> 4;

    const int lakk = tid & 15;
    const int lamm = tid >> 4;
    const int lbnn = tid & 127;
    const int lbk0 = (tid >> 7) << 3;

    float2 acc[8][4];
#pragma unroll
    for (int j = 0; j < 8; ++j)
#pragma unroll
        for (int p = 0; p < 4; ++p) acc[j][p] = make_float2(0.f, 0.f);

    float ra[8], rb[8];

    auto loadA = [&](int k0) {
        int p = k0 >> 7;
        int f = (k0 & 127) + lakk;
        size_t colofs = (size_t)p * (TT * FF) + (size_t)t * FF + f;
#pragma unroll
        for (int i = 0; i < 8; ++i)
            ra[i] = X[(size_t)(bb0 + lamm + 16 * i) * (PP * TT * FF) + colofs];
    };
    auto loadB = [&](int k0) {
#pragma unroll
        for (int i = 0; i < 8; ++i)
            rb[i] = Wx[(size_t)(k0 + lbk0 + i) * G4 + n0 + lbnn];
    };
    auto stsAB = [&](int buf) {
#pragma unroll
        for (int i = 0; i < 8; ++i) a_s[buf][lakk][lamm + 16 * i] = ra[i];
#pragma unroll
        for (int i = 0; i < 8; ++i) b_s[buf][lbk0 + i][lbnn] = rb[i];
    };

    const int NS = DD / KT1;
    loadA(0); loadB(0);
    stsAB(0);
    __syncthreads();

    for (int s = 0; s < NS; ++s) {
        const int buf = s & 1;
        if (s + 1 < NS) { loadA((s + 1) * KT1); loadB((s + 1) * KT1); }
#pragma unroll
        for (int kk = 0; kk < KT1; ++kk) {
            float2 a01 = *(const float2*)&a_s[buf][kk][ty * 8 + 0];
            float2 a23 = *(const float2*)&a_s[buf][kk][ty * 8 + 2];
            float2 a45 = *(const float2*)&a_s[buf][kk][ty * 8 + 4];
            float2 a67 = *(const float2*)&a_s[buf][kk][ty * 8 + 6];
#pragma unroll
            for (int j = 0; j < 8; ++j) {
                float bv = b_s[buf][kk][tx + 16 * j];
                float2 bb = make_float2(bv, bv);
                acc[j][0] = ffma2(a01, bb, acc[j][0]);
                acc[j][1] = ffma2(a23, bb, acc[j][1]);
                acc[j][2] = ffma2(a45, bb, acc[j][2]);
                acc[j][3] = ffma2(a67, bb, acc[j][3]);
            }
        }
        if (s + 1 < NS) stsAB(buf ^ 1);
        __syncthreads();
    }

    const int mrow = by * 128 + ty * 8;
#pragma unroll
    for (int j = 0; j < 8; ++j) {
        int n = n0 + tx + 16 * j;
        float bn = bvec[n];
#pragma unroll
        for (int p = 0; p < 4; ++p) {
            size_t o = (size_t)(mrow + 2 * p) * G4 + n;
            g_xw[o]      = acc[j][p].x + bn;
            g_xw[o + G4] = acc[j][p].y + bn;
        }
    }
}

// ---------------------------------------------------------------------------
// Phase 2 (PERSISTENT v2): whole recurrence in one kernel.
//   Grid (4, 32) = 128 blocks, 512 threads. Block: 64 rows x 16 ch (x4 gates).
//   Wh slice gate-interleaved in smem (128 KB, resident all steps).
//   h-tile staged in smem PRE-DUPLICATED {v,v} -> LDS.128 = 2 ready dup pairs.
//   Accumulators packed over gate pairs (i,f)/(g,o) -> b pairs come straight
//   from one gate-interleaved LDS.128. Inner kk: 2 LDS.128 + 4 FFMA2, 0 MOV.
//   Per-row-group barrier (32 blocks) instead of global.
// ---------------------------------------------------------------------------
#define WS_FLOATS (512 * 64)            // Wh slice [k][chl*4+gate]
#define AS_FLOATS (64 * 128)            // one dup h-chunk [k][row*2]
#define SMEM_BYTES ((WS_FLOATS + 2 * AS_FLOATS) * 4)   // 196608 B

__global__ void __launch_bounds__(512, 1)
plstm_persist(const float* __restrict__ Wh, const float* __restrict__ tau,
              const float* __restrict__ shift) {
    extern __shared__ float smem[];
    float* ws = smem;                     // [512][64]
    float* as = smem + WS_FLOATS;         // [2][64][128] duplicated

    const int tid  = threadIdx.x;
    const int m0   = blockIdx.x << 6;     // 4 row groups of 64
    const int ch0  = blockIdx.y << 4;     // 32 channel tiles of 16
    const int w    = tid >> 5;            // 0..15
    const int lane = tid & 31;
    const int rp   = lane >> 4;           // 0/1 row-pair select
    const int chl  = lane & 15;
    const int mb   = w * 4 + rp * 2;      // local rows mb, mb+1
    const int ch   = ch0 + chl;

    // ---- prologue: Wh slice -> smem, gate-interleaved [k][chl*4+gate] ----
    for (int idx = tid; idx < 512 * 16; idx += 512) {
        int k    = idx >> 4;
        int seg  = idx & 15;
        int g    = seg >> 2;
        int part = seg & 3;
        float4 v = *(const float4*)&Wh[(size_t)k * G4 + g * HH + ch0 + part * 4];
        float* dst = &ws[k * 64];
        dst[(part * 4 + 0) * 4 + g] = v.x;
        dst[(part * 4 + 1) * 4 + g] = v.y;
        dst[(part * 4 + 2) * 4 + g] = v.z;
        dst[(part * 4 + 3) * 4 + g] = v.w;
    }

    const float tv = tau[ch];
    const float sv = shift[ch];

    // persistent per-thread state (2 rows)
    float creg[2] = {0.f, 0.f};
    float hreg[2] = {0.f, 0.f};

    // h-chunk loader: row = tid&63, 8 k's per thread (hks)
    const int hrow = tid & 63;
    const int hks  = (tid >> 6) << 3;
    float4 hv0, hv1;

    unsigned* bar = &g_bar4[blockIdx.x];

    __syncthreads();   // ws ready

    for (int t = 0; t < TT; ++t) {
        const float* __restrict__ hin = g_h[t & 1];

        // prefetch this step's xw into registers (hidden under GEMM)
        float xwv[2][4];
#pragma unroll
        for (int r = 0; r < 2; ++r) {
            const float* xp = &g_xw[(size_t)t * BB * G4 + (size_t)(m0 + mb + r) * G4 + ch];
            xwv[r][0] = xp[0];
            xwv[r][1] = xp[512];
            xwv[r][2] = xp[1024];
            xwv[r][3] = xp[1536];
        }

        auto loadH = [&](int k0) {
            const float* hp = &hin[(size_t)(m0 + hrow) * HH + k0 + hks];
            hv0 = *(const float4*)&hp[0];
            hv1 = *(const float4*)&hp[4];
        };
        auto stsH = [&](int buf) {
            float* base = &as[buf * AS_FLOATS + hrow * 2];
            *(float2*)&base[(hks + 0) * 128] = make_float2(hv0.x, hv0.x);
            *(float2*)&base[(hks + 1) * 128] = make_float2(hv0.y, hv0.y);
            *(float2*)&base[(hks + 2) * 128] = make_float2(hv0.z, hv0.z);
            *(float2*)&base[(hks + 3) * 128] = make_float2(hv0.w, hv0.w);
            *(float2*)&base[(hks + 4) * 128] = make_float2(hv1.x, hv1.x);
            *(float2*)&base[(hks + 5) * 128] = make_float2(hv1.y, hv1.y);
            *(float2*)&base[(hks + 6) * 128] = make_float2(hv1.z, hv1.z);
            *(float2*)&base[(hks + 7) * 128] = make_float2(hv1.w, hv1.w);
        };

        float2 acc_if[2], acc_go[2];
#pragma unroll
        for (int r = 0; r < 2; ++r) {
            acc_if[r] = make_float2(0.f, 0.f);
            acc_go[r] = make_float2(0.f, 0.f);
        }

        loadH(0);
        stsH(0);
        __syncthreads();

        for (int c = 0; c < 8; ++c) {
            const int buf = c & 1;
            if (c < 7) loadH((c + 1) * 64);
            const float* wsb = &ws[(c * 64) * 64 + chl * 4];
            const float* asb = &as[buf * AS_FLOATS + mb * 2];
#pragma unroll 16
            for (int kk = 0; kk < 64; ++kk) {
                float4 ad = *(const float4*)&asb[kk * 128];   // {h0,h0,h1,h1}
                float4 wq = *(const float4*)&wsb[kk * 64];    // {wi,wf,wg,wo}
                float2 a0 = make_float2(ad.x, ad.y);          // dup pair, no MOV
                float2 a1 = make_float2(ad.z, ad.w);
                float2 bif = make_float2(wq.x, wq.y);
                float2 bgo = make_float2(wq.z, wq.w);
                acc_if[0] = ffma2(a0, bif, acc_if[0]);
                acc_go[0] = ffma2(a0, bgo, acc_go[0]);
                acc_if[1] = ffma2(a1, bif, acc_if[1]);
                acc_go[1] = ffma2(a1, bgo, acc_go[1]);
            }
            if (c < 7) stsH(buf ^ 1);
            __syncthreads();
        }

        // ---- fused epilogue ----
        float xph = ((float)t - sv) / tv;
        float phi = xph - floorf(xph);
        float kg = (phi < 0.025f) ? (40.0f * phi)
                 : (phi < 0.05f)  ? (2.0f - 40.0f * phi)
                                  : (0.001f * phi);

        float* __restrict__ hout = g_h[(t + 1) & 1];
#pragma unroll
        for (int r = 0; r < 2; ++r) {
            float gi = acc_if[r].x + xwv[r][0];
            float gf = acc_if[r].y + xwv[r][1];
            float gg = acc_go[r].x + xwv[r][2];
            float go = acc_go[r].y + xwv[r][3];
            gi = 1.0f / (1.0f + __expf(-gi));
            gf = 1.0f / (1.0f + __expf(-gf));
            gg = tanhf(gg);
            go = 1.0f / (1.0f + __expf(-go));
            float cold = creg[r];
            float ct = gf * cold + gi * gg;
            float ht = go * tanhf(ct);
            creg[r] = kg * ct + (1.0f - kg) * cold;
            float hn = kg * ht + (1.0f - kg) * hreg[r];
            hreg[r] = hn;
            hout[(size_t)(m0 + mb + r) * HH + ch] = hn;
        }

        // ---- per-row-group barrier over 32 blocks (skip after final step) ----
        if (t < TT - 1) {
            __syncthreads();
            if (tid == 0) {
                __threadfence();
                atomicAdd(bar, 1u);
                const unsigned target = (unsigned)(t + 1) * 32u;
                unsigned v;
                do {
                    asm volatile("ld.acquire.gpu.global.u32 %0, [%1];"
                                 : "=r"(v) : "l"(bar) : "memory");
                    if (v >= target) break;
                    __nanosleep(32);
                } while (true);
            }
            __syncthreads();
        }
    }
}

// ---------------------------------------------------------------------------
// Phase 3: logits = hT @ fc_w + fc_b; log_softmax over C=60.
// 256 threads/block: 4 k-partials per class in parallel.
// ---------------------------------------------------------------------------
__global__ void head_kernel(const float* __restrict__ fc_w,
                            const float* __restrict__ fc_b,
                            float* __restrict__ out) {
    __shared__ float hrow[HH];
    __shared__ float part[CC][4];
    __shared__ float logits[CC];
    __shared__ float s_lse;
    const int b = blockIdx.x;
    const int tid = threadIdx.x;   // 256 threads

    *(float2*)&hrow[tid * 2] = *(const float2*)&g_h[0][(size_t)b * HH + tid * 2];
    __syncthreads();

    const int c = tid >> 2;
    const int s = tid & 3;
    if (c < CC) {
        float sum = 0.0f;
        const float* wp = &fc_w[(size_t)(s * 128) * CC + c];
        const float* hp = &hrow[s * 128];
#pragma unroll 8
        for (int k = 0; k < 128; ++k) sum += hp[k] * wp[k * CC];
        part[c][s] = sum;
    }
    __syncthreads();

    if (tid < CC)
        logits[tid] = part[tid][0] + part[tid][1] + part[tid][2] + part[tid][3] + fc_b[tid];
    __syncthreads();

    if (tid == 0) {
        float mx = -1e30f;
        for (int i = 0; i < CC; ++i) mx = fmaxf(mx, logits[i]);
        float sm = 0.0f;
        for (int i = 0; i < CC; ++i) sm += expf(logits[i] - mx);
        s_lse = mx + logf(sm);
    }
    __syncthreads();

    if (tid < CC) out[(size_t)b * CC + tid] = logits[tid] - s_lse;
}

// ---------------------------------------------------------------------------
// Launch
// ---------------------------------------------------------------------------
extern "C" void kernel_launch(void* const* d_in, const int* in_sizes, int n_in,
                              void* d_out, int out_size) {
    const float* x     = (const float*)d_in[0];
    const float* Wx    = (const float*)d_in[1];
    const float* Wh    = (const float*)d_in[2];
    const float* bias  = (const float*)d_in[3];
    const float* tau   = (const float*)d_in[4];
    const float* shift = (const float*)d_in[5];
    const float* fc_w  = (const float*)d_in[6];
    const float* fc_b  = (const float*)d_in[7];
    float* out = (float*)d_out;

    cudaFuncSetAttribute(plstm_persist,
                         cudaFuncAttributeMaxDynamicSharedMemorySize, SMEM_BYTES);

    zero_state<<<(BB * HH + 255) / 256, 256>>>();

    dim3 g1(G4 / 128, (TT * BB) / 128);   // (16, 512)
    xw_gemm<<<g1, 256>>>(x, Wx, bias);

    dim3 g2(4, 32);                        // 128 persistent blocks
    plstm_persist<<<g2, 512, SMEM_BYTES>>>(Wh, tau, shift);

    head_kernel<<<BB, 256>>>(fc_w, fc_b, out);
}

// round 9
// speedup vs baseline: 1.1629x; 1.1629x over previous
#include <cuda_runtime.h>
#include <math.h>

// Problem constants
#define BB 256
#define PP 5
#define TT 256
#define FF 128
#define HH 512
#define CC 60
#define DD 640      // P*F
#define G4 2048     // 4*H

// Scratch state (device globals: allocation-free per harness rules)
__device__ float g_xw[134217728ULL];   // (T*B, 4H) = 65536 x 2048 fp32
__device__ float g_h[2][BB * HH];      // double-buffered hidden state
__device__ unsigned g_bar4[4];         // per-row-group barrier counters

// ---------------------------------------------------------------------------
// Packed fp32x2 FMA (SASS FFMA2)
// ---------------------------------------------------------------------------
__device__ __forceinline__ float2 ffma2(float2 a, float2 b, float2 c) {
    unsigned long long ua = *reinterpret_cast<unsigned long long*>(&a);
    unsigned long long ub = *reinterpret_cast<unsigned long long*>(&b);
    unsigned long long uc = *reinterpret_cast<unsigned long long*>(&c);
    unsigned long long ud;
    asm("fma.rn.f32x2 %0, %1, %2, %3;" : "=l"(ud) : "l"(ua), "l"(ub), "l"(uc));
    return *reinterpret_cast<float2*>(&ud);
}

// ---------------------------------------------------------------------------
// Zero initial state + reset barriers (runs every launch)
// ---------------------------------------------------------------------------
__global__ void zero_state() {
    int i = blockIdx.x * blockDim.x + threadIdx.x;
    if (i < BB * HH) g_h[0][i] = 0.0f;
    if (i < 4) g_bar4[i] = 0u;
}

// ---------------------------------------------------------------------------
// Phase 1: XW[t*B+b, :] = x_seq[t,b,:] @ Wx + bias  (unchanged — near peak)
// ---------------------------------------------------------------------------
#define KT1 16
__global__ void __launch_bounds__(256, 2)
xw_gemm(const float* __restrict__ X, const float* __restrict__ Wx,
        const float* __restrict__ bvec) {
    __shared__ float a_s[2][KT1][130];
    __shared__ float b_s[2][KT1][128];

    const int tid = threadIdx.x;
    const int by  = blockIdx.y;
    const int n0  = blockIdx.x << 7;
    const int t   = by >> 1;
    const int bb0 = (by & 1) << 7;

    const int tx = tid & 15;
    const int ty = tid >> 4;

    const int lakk = tid & 15;
    const int lamm = tid >> 4;
    const int lbnn = tid & 127;
    const int lbk0 = (tid >> 7) << 3;

    float2 acc[8][4];
#pragma unroll
    for (int j = 0; j < 8; ++j)
#pragma unroll
        for (int p = 0; p < 4; ++p) acc[j][p] = make_float2(0.f, 0.f);

    float ra[8], rb[8];

    auto loadA = [&](int k0) {
        int p = k0 >> 7;
        int f = (k0 & 127) + lakk;
        size_t colofs = (size_t)p * (TT * FF) + (size_t)t * FF + f;
#pragma unroll
        for (int i = 0; i < 8; ++i)
            ra[i] = X[(size_t)(bb0 + lamm + 16 * i) * (PP * TT * FF) + colofs];
    };
    auto loadB = [&](int k0) {
#pragma unroll
        for (int i = 0; i < 8; ++i)
            rb[i] = Wx[(size_t)(k0 + lbk0 + i) * G4 + n0 + lbnn];
    };
    auto stsAB = [&](int buf) {
#pragma unroll
        for (int i = 0; i < 8; ++i) a_s[buf][lakk][lamm + 16 * i] = ra[i];
#pragma unroll
        for (int i = 0; i < 8; ++i) b_s[buf][lbk0 + i][lbnn] = rb[i];
    };

    const int NS = DD / KT1;
    loadA(0); loadB(0);
    stsAB(0);
    __syncthreads();

    for (int s = 0; s < NS; ++s) {
        const int buf = s & 1;
        if (s + 1 < NS) { loadA((s + 1) * KT1); loadB((s + 1) * KT1); }
#pragma unroll
        for (int kk = 0; kk < KT1; ++kk) {
            float2 a01 = *(const float2*)&a_s[buf][kk][ty * 8 + 0];
            float2 a23 = *(const float2*)&a_s[buf][kk][ty * 8 + 2];
            float2 a45 = *(const float2*)&a_s[buf][kk][ty * 8 + 4];
            float2 a67 = *(const float2*)&a_s[buf][kk][ty * 8 + 6];
#pragma unroll
            for (int j = 0; j < 8; ++j) {
                float bv = b_s[buf][kk][tx + 16 * j];
                float2 bb = make_float2(bv, bv);
                acc[j][0] = ffma2(a01, bb, acc[j][0]);
                acc[j][1] = ffma2(a23, bb, acc[j][1]);
                acc[j][2] = ffma2(a45, bb, acc[j][2]);
                acc[j][3] = ffma2(a67, bb, acc[j][3]);
            }
        }
        if (s + 1 < NS) stsAB(buf ^ 1);
        __syncthreads();
    }

    const int mrow = by * 128 + ty * 8;
#pragma unroll
    for (int j = 0; j < 8; ++j) {
        int n = n0 + tx + 16 * j;
        float bn = bvec[n];
#pragma unroll
        for (int p = 0; p < 4; ++p) {
            size_t o = (size_t)(mrow + 2 * p) * G4 + n;
            g_xw[o]      = acc[j][p].x + bn;
            g_xw[o + G4] = acc[j][p].y + bn;
        }
    }
}

// ---------------------------------------------------------------------------
// Phase 2 (PERSISTENT v3): whole recurrence in one kernel.
//   Grid (4, 32) = 128 blocks, 256 threads (8 warps). Block: 64 rows x 16 ch.
//   Thread: 4 rows x 1 ch x 4 gates -> 8 FFMA2 per kk.
//   Warp layout: 8 channels x 4 row-groups:
//     - wq (gate-interleaved Wh) read = 128 B contiguous per warp = 1 wavefront
//     - two a-dup reads = 4 distinct 16B lines each = 1 wavefront each
//   h staged in smem PRE-DUPLICATED {v,v}; accumulators packed over gate pairs
//   (i,f)/(g,o): zero duplication MOVs anywhere in the inner loop.
//   Inner kk: 3 LDS.128 + 8 FFMA2 = 11 instructions, ~3 wavefronts.
// ---------------------------------------------------------------------------
#define WS_FLOATS (512 * 64)            // Wh slice [k][chl*4+gate]
#define AS_FLOATS (64 * 128)            // one dup h-chunk [k][row*2]
#define SMEM_BYTES ((WS_FLOATS + 2 * AS_FLOATS) * 4)   // 196608 B

__global__ void __launch_bounds__(256, 1)
plstm_persist(const float* __restrict__ Wh, const float* __restrict__ tau,
              const float* __restrict__ shift) {
    extern __shared__ float smem[];
    float* ws = smem;                     // [512][64]
    float* as = smem + WS_FLOATS;         // [2][64][128] duplicated

    const int tid  = threadIdx.x;
    const int m0   = blockIdx.x << 6;     // 4 row groups of 64
    const int ch0  = blockIdx.y << 4;     // 32 channel tiles of 16
    const int w    = tid >> 5;            // 0..7
    const int lane = tid & 31;
    const int chl  = ((w & 1) << 3) | (lane & 7);   // 0..15, contiguous 8 per warp
    const int rg   = lane >> 3;                     // 0..3 row-group within warp
    const int mb   = ((w >> 1) << 4) + (rg << 2);   // local rows mb..mb+3
    const int ch   = ch0 + chl;

    // ---- prologue: Wh slice -> smem, gate-interleaved [k][chl*4+gate] ----
    for (int idx = tid; idx < 512 * 16; idx += 256) {
        int k    = idx >> 4;
        int seg  = idx & 15;
        int g    = seg >> 2;
        int part = seg & 3;
        float4 v = *(const float4*)&Wh[(size_t)k * G4 + g * HH + ch0 + part * 4];
        float* dst = &ws[k * 64];
        dst[(part * 4 + 0) * 4 + g] = v.x;
        dst[(part * 4 + 1) * 4 + g] = v.y;
        dst[(part * 4 + 2) * 4 + g] = v.z;
        dst[(part * 4 + 3) * 4 + g] = v.w;
    }

    const float tv = tau[ch];
    const float sv = shift[ch];

    // persistent per-thread state (4 rows)
    float creg[4] = {0.f, 0.f, 0.f, 0.f};
    float hreg[4] = {0.f, 0.f, 0.f, 0.f};

    // h-chunk loader: row = tid&63, 16 k's per thread starting at hq*16
    const int hrow = tid & 63;
    const int hq   = tid >> 6;            // 0..3
    float4 hv[4];

    unsigned* bar = &g_bar4[blockIdx.x];

    __syncthreads();   // ws ready

    for (int t = 0; t < TT; ++t) {
        const float* __restrict__ hin = g_h[t & 1];

        // prefetch this step's xw into registers (consumed in epilogue)
        float2 xif[4], xgo[4];
#pragma unroll
        for (int r = 0; r < 4; ++r) {
            const float* xp = &g_xw[(size_t)t * BB * G4 + (size_t)(m0 + mb + r) * G4 + ch];
            xif[r] = make_float2(xp[0], xp[512]);
            xgo[r] = make_float2(xp[1024], xp[1536]);
        }

        auto loadH = [&](int k0) {
            const float* hp = &hin[(size_t)(m0 + hrow) * HH + k0 + hq * 16];
            hv[0] = *(const float4*)&hp[0];
            hv[1] = *(const float4*)&hp[4];
            hv[2] = *(const float4*)&hp[8];
            hv[3] = *(const float4*)&hp[12];
        };
        auto stsH = [&](int buf) {
            float* base = &as[buf * AS_FLOATS + hrow * 2];
#pragma unroll
            for (int i = 0; i < 4; ++i) {
                int k = hq * 16 + i * 4;
                float4 v = hv[i];
                *(float2*)&base[(k + 0) * 128] = make_float2(v.x, v.x);
                *(float2*)&base[(k + 1) * 128] = make_float2(v.y, v.y);
                *(float2*)&base[(k + 2) * 128] = make_float2(v.z, v.z);
                *(float2*)&base[(k + 3) * 128] = make_float2(v.w, v.w);
            }
        };

        float2 acc_if[4], acc_go[4];
#pragma unroll
        for (int r = 0; r < 4; ++r) {
            acc_if[r] = make_float2(0.f, 0.f);
            acc_go[r] = make_float2(0.f, 0.f);
        }

        loadH(0);
        stsH(0);
        __syncthreads();

        for (int c = 0; c < 8; ++c) {
            const int buf = c & 1;
            if (c < 7) loadH((c + 1) * 64);
            const float* wsb = &ws[(c * 64) * 64 + chl * 4];
            const float* asb = &as[buf * AS_FLOATS + mb * 2];
#pragma unroll 8
            for (int kk = 0; kk < 64; ++kk) {
                float4 ad0 = *(const float4*)&asb[kk * 128];       // {h0,h0,h1,h1}
                float4 ad1 = *(const float4*)&asb[kk * 128 + 4];   // {h2,h2,h3,h3}
                float4 wq  = *(const float4*)&wsb[kk * 64];        // {wi,wf,wg,wo}
                float2 bif = make_float2(wq.x, wq.y);              // aligned halves, no MOV
                float2 bgo = make_float2(wq.z, wq.w);
                acc_if[0] = ffma2(make_float2(ad0.x, ad0.y), bif, acc_if[0]);
                acc_go[0] = ffma2(make_float2(ad0.x, ad0.y), bgo, acc_go[0]);
                acc_if[1] = ffma2(make_float2(ad0.z, ad0.w), bif, acc_if[1]);
                acc_go[1] = ffma2(make_float2(ad0.z, ad0.w), bgo, acc_go[1]);
                acc_if[2] = ffma2(make_float2(ad1.x, ad1.y), bif, acc_if[2]);
                acc_go[2] = ffma2(make_float2(ad1.x, ad1.y), bgo, acc_go[2]);
                acc_if[3] = ffma2(make_float2(ad1.z, ad1.w), bif, acc_if[3]);
                acc_go[3] = ffma2(make_float2(ad1.z, ad1.w), bgo, acc_go[3]);
            }
            if (c < 7) stsH(buf ^ 1);
            __syncthreads();
        }

        // ---- fused epilogue ----
        float xph = ((float)t - sv) / tv;
        float phi = xph - floorf(xph);
        float kg = (phi < 0.025f) ? (40.0f * phi)
                 : (phi < 0.05f)  ? (2.0f - 40.0f * phi)
                                  : (0.001f * phi);

        float* __restrict__ hout = g_h[(t + 1) & 1];
#pragma unroll
        for (int r = 0; r < 4; ++r) {
            float gi = acc_if[r].x + xif[r].x;
            float gf = acc_if[r].y + xif[r].y;
            float gg = acc_go[r].x + xgo[r].x;
            float go = acc_go[r].y + xgo[r].y;
            gi = 1.0f / (1.0f + __expf(-gi));
            gf = 1.0f / (1.0f + __expf(-gf));
            gg = tanhf(gg);
            go = 1.0f / (1.0f + __expf(-go));
            float cold = creg[r];
            float ct = gf * cold + gi * gg;
            float ht = go * tanhf(ct);
            creg[r] = kg * ct + (1.0f - kg) * cold;
            float hn = kg * ht + (1.0f - kg) * hreg[r];
            hreg[r] = hn;
            hout[(size_t)(m0 + mb + r) * HH + ch] = hn;
        }

        // ---- per-row-group barrier over 32 blocks (skip after final step) ----
        if (t < TT - 1) {
            __syncthreads();
            if (tid == 0) {
                __threadfence();
                atomicAdd(bar, 1u);
                const unsigned target = (unsigned)(t + 1) * 32u;
                unsigned v;
                do {
                    asm volatile("ld.acquire.gpu.global.u32 %0, [%1];"
                                 : "=r"(v) : "l"(bar) : "memory");
                    if (v >= target) break;
                    __nanosleep(32);
                } while (true);
            }
            __syncthreads();
        }
    }
}

// ---------------------------------------------------------------------------
// Phase 3: logits = hT @ fc_w + fc_b; log_softmax over C=60.
// 256 threads/block: 4 k-partials per class in parallel.
// ---------------------------------------------------------------------------
__global__ void head_kernel(const float* __restrict__ fc_w,
                            const float* __restrict__ fc_b,
                            float* __restrict__ out) {
    __shared__ float hrow[HH];
    __shared__ float part[CC][4];
    __shared__ float logits[CC];
    __shared__ float s_lse;
    const int b = blockIdx.x;
    const int tid = threadIdx.x;   // 256 threads

    *(float2*)&hrow[tid * 2] = *(const float2*)&g_h[0][(size_t)b * HH + tid * 2];
    __syncthreads();

    const int c = tid >> 2;
    const int s = tid & 3;
    if (c < CC) {
        float sum = 0.0f;
        const float* wp = &fc_w[(size_t)(s * 128) * CC + c];
        const float* hp = &hrow[s * 128];
#pragma unroll 16
        for (int k = 0; k < 128; ++k) sum += hp[k] * wp[k * CC];
        part[c][s] = sum;
    }
    __syncthreads();

    if (tid < CC)
        logits[tid] = part[tid][0] + part[tid][1] + part[tid][2] + part[tid][3] + fc_b[tid];
    __syncthreads();

    if (tid == 0) {
        float mx = -1e30f;
        for (int i = 0; i < CC; ++i) mx = fmaxf(mx, logits[i]);
        float sm = 0.0f;
        for (int i = 0; i < CC; ++i) sm += expf(logits[i] - mx);
        s_lse = mx + logf(sm);
    }
    __syncthreads();

    if (tid < CC) out[(size_t)b * CC + tid] = logits[tid] - s_lse;
}

// ---------------------------------------------------------------------------
// Launch
// ---------------------------------------------------------------------------
extern "C" void kernel_launch(void* const* d_in, const int* in_sizes, int n_in,
                              void* d_out, int out_size) {
    const float* x     = (const float*)d_in[0];
    const float* Wx    = (const float*)d_in[1];
    const float* Wh    = (const float*)d_in[2];
    const float* bias  = (const float*)d_in[3];
    const float* tau   = (const float*)d_in[4];
    const float* shift = (const float*)d_in[5];
    const float* fc_w  = (const float*)d_in[6];
    const float* fc_b  = (const float*)d_in[7];
    float* out = (float*)d_out;

    cudaFuncSetAttribute(plstm_persist,
                         cudaFuncAttributeMaxDynamicSharedMemorySize, SMEM_BYTES);

    zero_state<<<(BB * HH + 255) / 256, 256>>>();

    dim3 g1(G4 / 128, (TT * BB) / 128);   // (16, 512)
    xw_gemm<<<g1, 256>>>(x, Wx, bias);

    dim3 g2(4, 32);                        // 128 persistent blocks
    plstm_persist<<<g2, 256, SMEM_BYTES>>>(Wh, tau, shift);

    head_kernel<<<BB, 256>>>(fc_w, fc_b, out);
}

// round 12
// speedup vs baseline: 1.2259x; 1.0541x over previous
#include <cuda_runtime.h>
#include <cuda_bf16.h>
#include <math.h>
#include <stdint.h>

// Problem constants
#define BB 256
#define PP 5
#define TT 256
#define FF 128
#define HH 512
#define CC 60
#define DD 640      // P*F
#define G4 2048     // 4*H

// Scratch (device globals: allocation-free per harness rules)
__device__ float g_xw[134217728ULL];   // (T*B, 4H) fp32
__device__ float g_h[2][BB * HH];      // double-buffered hidden state (fp32)
__device__ float g_kg[TT * HH];        // precomputed time gate k(t,ch)
__device__ unsigned g_bar2[2];         // per-m-group barrier counters

// ---------------------------------------------------------------------------
// FFMA2 helper (xw_gemm only)
// ---------------------------------------------------------------------------
__device__ __forceinline__ float2 ffma2(float2 a, float2 b, float2 c) {
    unsigned long long ua = *reinterpret_cast<unsigned long long*>(&a);
    unsigned long long ub = *reinterpret_cast<unsigned long long*>(&b);
    unsigned long long uc = *reinterpret_cast<unsigned long long*>(&c);
    unsigned long long ud;
    asm("fma.rn.f32x2 %0, %1, %2, %3;" : "=l"(ud) : "l"(ua), "l"(ub), "l"(uc));
    return *reinterpret_cast<float2*>(&ud);
}

// ---------------------------------------------------------------------------
// Warp-level MMA helpers (arch-portable: ldmatrix + mma.sync -> HMMA SASS)
// ---------------------------------------------------------------------------
__device__ __forceinline__ void ldsm4(unsigned* r, uint32_t addr) {
    asm volatile("ldmatrix.sync.aligned.m8n8.x4.shared.b16 {%0, %1, %2, %3}, [%4];"
                 : "=r"(r[0]), "=r"(r[1]), "=r"(r[2]), "=r"(r[3]) : "r"(addr));
}

__device__ __forceinline__ void mma_bf16(float* d, const unsigned* a, const unsigned* b) {
    asm volatile(
        "mma.sync.aligned.m16n8k16.row.col.f32.bf16.bf16.f32 "
        "{%0, %1, %2, %3}, {%4, %5, %6, %7}, {%8, %9}, {%0, %1, %2, %3};"
        : "+f"(d[0]), "+f"(d[1]), "+f"(d[2]), "+f"(d[3])
        : "r"(a[0]), "r"(a[1]), "r"(a[2]), "r"(a[3]), "r"(b[0]), "r"(b[1]));
}

__device__ __forceinline__ unsigned pack_bf16(__nv_bfloat16 lo, __nv_bfloat16 hi) {
    return (unsigned)__bfloat16_as_ushort(lo) | ((unsigned)__bfloat16_as_ushort(hi) << 16);
}

// ---------------------------------------------------------------------------
// Init kernels
// ---------------------------------------------------------------------------
__global__ void zero_state() {
    int i = blockIdx.x * blockDim.x + threadIdx.x;
    if (i < BB * HH) g_h[0][i] = 0.0f;
    if (i < 2) g_bar2[i] = 0u;
}

__global__ void kg_kernel(const float* __restrict__ tau,
                          const float* __restrict__ shift) {
    int i = blockIdx.x * blockDim.x + threadIdx.x;
    if (i < TT * HH) {
        int t = i >> 9, ch = i & 511;
        float tv = tau[ch], sv = shift[ch];
        float xph = ((float)t - sv) / tv;
        float phi = xph - floorf(xph);
        float kg = (phi < 0.025f) ? (40.0f * phi)
                 : (phi < 0.05f)  ? (2.0f - 40.0f * phi)
                                  : (0.001f * phi);
        g_kg[i] = kg;
    }
}

// ---------------------------------------------------------------------------
// Phase 1: XW GEMM (FFMA2, unchanged — near peak)
// ---------------------------------------------------------------------------
#define KT1 16
__global__ void __launch_bounds__(256, 2)
xw_gemm(const float* __restrict__ X, const float* __restrict__ Wx,
        const float* __restrict__ bvec) {
    __shared__ float a_s[2][KT1][130];
    __shared__ float b_s[2][KT1][128];

    const int tid = threadIdx.x;
    const int by  = blockIdx.y;
    const int n0  = blockIdx.x << 7;
    const int t   = by >> 1;
    const int bb0 = (by & 1) << 7;
    const int tx = tid & 15;
    const int ty = tid >> 4;
    const int lakk = tid & 15;
    const int lamm = tid >> 4;
    const int lbnn = tid & 127;
    const int lbk0 = (tid >> 7) << 3;

    float2 acc[8][4];
#pragma unroll
    for (int j = 0; j < 8; ++j)
#pragma unroll
        for (int p = 0; p < 4; ++p) acc[j][p] = make_float2(0.f, 0.f);

    float ra[8], rb[8];
    auto loadA = [&](int k0) {
        int p = k0 >> 7;
        int f = (k0 & 127) + lakk;
        size_t colofs = (size_t)p * (TT * FF) + (size_t)t * FF + f;
#pragma unroll
        for (int i = 0; i < 8; ++i)
            ra[i] = X[(size_t)(bb0 + lamm + 16 * i) * (PP * TT * FF) + colofs];
    };
    auto loadB = [&](int k0) {
#pragma unroll
        for (int i = 0; i < 8; ++i)
            rb[i] = Wx[(size_t)(k0 + lbk0 + i) * G4 + n0 + lbnn];
    };
    auto stsAB = [&](int buf) {
#pragma unroll
        for (int i = 0; i < 8; ++i) a_s[buf][lakk][lamm + 16 * i] = ra[i];
#pragma unroll
        for (int i = 0; i < 8; ++i) b_s[buf][lbk0 + i][lbnn] = rb[i];
    };

    const int NS = DD / KT1;
    loadA(0); loadB(0);
    stsAB(0);
    __syncthreads();

    for (int s = 0; s < NS; ++s) {
        const int buf = s & 1;
        if (s + 1 < NS) { loadA((s + 1) * KT1); loadB((s + 1) * KT1); }
#pragma unroll
        for (int kk = 0; kk < KT1; ++kk) {
            float2 a01 = *(const float2*)&a_s[buf][kk][ty * 8 + 0];
            float2 a23 = *(const float2*)&a_s[buf][kk][ty * 8 + 2];
            float2 a45 = *(const float2*)&a_s[buf][kk][ty * 8 + 4];
            float2 a67 = *(const float2*)&a_s[buf][kk][ty * 8 + 6];
#pragma unroll
            for (int j = 0; j < 8; ++j) {
                float bv = b_s[buf][kk][tx + 16 * j];
                float2 bb = make_float2(bv, bv);
                acc[j][0] = ffma2(a01, bb, acc[j][0]);
                acc[j][1] = ffma2(a23, bb, acc[j][1]);
                acc[j][2] = ffma2(a45, bb, acc[j][2]);
                acc[j][3] = ffma2(a67, bb, acc[j][3]);
            }
        }
        if (s + 1 < NS) stsAB(buf ^ 1);
        __syncthreads();
    }

    const int mrow = by * 128 + ty * 8;
#pragma unroll
    for (int j = 0; j < 8; ++j) {
        int n = n0 + tx + 16 * j;
        float bn = bvec[n];
#pragma unroll
        for (int p = 0; p < 4; ++p) {
            size_t o = (size_t)(mrow + 2 * p) * G4 + n;
            g_xw[o]      = acc[j][p].x + bn;
            g_xw[o + G4] = acc[j][p].y + bn;
        }
    }
}

// ---------------------------------------------------------------------------
// Phase 2: PERSISTENT recurrence on mma.sync (HMMA) with split-bf16.
//   Grid (32, 2) = 64 blocks, 256 threads (8 warps).
//   Block: M=128 rows x N=64 gate-major cols (n = gate*16 + chl), K=512.
//   D = Ahi*Bhi + Ahi*Blo + Alo*Bhi  (fp32 accumulate, ~2^-16 accuracy).
//   Wh (B^T, n-major, padded pitch) resident in smem hi/lo for all steps.
//   h (A) staged per 64-K chunk via register prefetch (R7-proven pattern).
//   Warp w: m-tile rows 16w..16w+15, all 8 n-tiles.
// ---------------------------------------------------------------------------
#define BPITCH 1040                      // bytes per BT row (520 bf16)
#define APITCH 144                       // bytes per A row (72 bf16)
#define SM_BH 0
#define SM_BL 66560                      // 64*1040
#define SM_AH 133120
#define SM_AL 151552                     // +128*144
#define SMEM_TOTAL 169984

__global__ void __launch_bounds__(256, 1)
plstm_mma(const float* __restrict__ Wh) {
    extern __shared__ char smc[];
    const uint32_t sb = (uint32_t)__cvta_generic_to_shared(smc);
    const int tid  = threadIdx.x;
    const int wid  = tid >> 5;
    const int lane = tid & 31;
    const int ng   = blockIdx.x;          // 0..31 channel tile (16 ch)
    const int mg   = blockIdx.y;          // 0..1  batch half
    const int m0   = mg << 7;
    const int ch0  = ng << 4;

    // ---- prologue: Wh -> smem BT[n][k] bf16 hi/lo, n = gate*16 + chl ----
    {
        const int n  = tid >> 2;                  // 0..63
        const int kq = (tid & 3) * 128;
        const int g  = n >> 4;
        const int chl = n & 15;
        const float* wp = &Wh[(size_t)kq * G4 + g * HH + ch0 + chl];
        char* bh = smc + SM_BH + n * BPITCH + kq * 2;
        char* bl = smc + SM_BL + n * BPITCH + kq * 2;
        for (int k = 0; k < 128; ++k) {
            float wv = wp[(size_t)k * G4];
            __nv_bfloat16 hi = __float2bfloat16(wv);
            __nv_bfloat16 lo = __float2bfloat16(wv - __bfloat162float(hi));
            *(__nv_bfloat16*)(bh + k * 2) = hi;
            *(__nv_bfloat16*)(bl + k * 2) = lo;
        }
    }
    __syncthreads();

    // ldmatrix address precompute
    const int a_row = wid * 16 + (lane & 7) + ((lane >> 3) & 1) * 8;
    const uint32_t aOffH = sb + SM_AH + a_row * APITCH + ((lane >> 4) & 1) * 16;
    const uint32_t aOffL = sb + SM_AL + a_row * APITCH + ((lane >> 4) & 1) * 16;
    const int b_row = (lane & 7) + ((lane >> 4) & 1) * 8;
    const uint32_t bOffH = sb + SM_BH + b_row * BPITCH + ((lane >> 3) & 1) * 16;
    const uint32_t bOffL = sb + SM_BL + b_row * BPITCH + ((lane >> 3) & 1) * 16;

    // A staging mapping: thread -> (row, k-half)
    const int sr = tid >> 1;               // 0..127
    const int sk = (tid & 1) * 32;         // 0 or 32 floats

    // epilogue mapping
    const int gr = lane >> 2;
    const int tc = lane & 3;
    const int rbase = wid * 16 + gr;

    float cs[8], hs[8];
#pragma unroll
    for (int j = 0; j < 8; ++j) { cs[j] = 0.f; hs[j] = 0.f; }

    unsigned* bar = &g_bar2[mg];
    float4 pf[8];

    for (int t = 0; t < TT; ++t) {
        const float* __restrict__ hin = g_h[t & 1];

        float d[8][4];
#pragma unroll
        for (int j = 0; j < 8; ++j)
#pragma unroll
            for (int q = 0; q < 4; ++q) d[j][q] = 0.f;

        // prefetch chunk 0
        {
            const float* hp = &hin[(size_t)(m0 + sr) * HH + sk];
#pragma unroll
            for (int j = 0; j < 8; ++j) pf[j] = ((const float4*)hp)[j];
        }

        for (int c = 0; c < 8; ++c) {
            // ---- STS staged chunk (convert fp32 -> hi/lo bf16) ----
            {
                unsigned uh[16], ul[16];
#pragma unroll
                for (int j = 0; j < 8; ++j) {
                    float4 v = pf[j];
                    __nv_bfloat16 h0 = __float2bfloat16(v.x);
                    __nv_bfloat16 h1 = __float2bfloat16(v.y);
                    __nv_bfloat16 h2 = __float2bfloat16(v.z);
                    __nv_bfloat16 h3 = __float2bfloat16(v.w);
                    uh[2*j]   = pack_bf16(h0, h1);
                    uh[2*j+1] = pack_bf16(h2, h3);
                    ul[2*j]   = pack_bf16(__float2bfloat16(v.x - __bfloat162float(h0)),
                                          __float2bfloat16(v.y - __bfloat162float(h1)));
                    ul[2*j+1] = pack_bf16(__float2bfloat16(v.z - __bfloat162float(h2)),
                                          __float2bfloat16(v.w - __bfloat162float(h3)));
                }
                char* ah = smc + SM_AH + sr * APITCH + sk * 2;
                char* al = smc + SM_AL + sr * APITCH + sk * 2;
#pragma unroll
                for (int q = 0; q < 4; ++q) {
                    *(uint4*)(ah + q * 16) = make_uint4(uh[4*q], uh[4*q+1], uh[4*q+2], uh[4*q+3]);
                    *(uint4*)(al + q * 16) = make_uint4(ul[4*q], ul[4*q+1], ul[4*q+2], ul[4*q+3]);
                }
            }
            __syncthreads();

            // prefetch next chunk (hidden under MMA)
            if (c < 7) {
                const float* hp = &hin[(size_t)(m0 + sr) * HH + (c + 1) * 64 + sk];
#pragma unroll
                for (int j = 0; j < 8; ++j) pf[j] = ((const float4*)hp)[j];
            }

            // ---- compute: 4 k16-steps over this 64-K chunk ----
#pragma unroll
            for (int ks = 0; ks < 4; ++ks) {
                unsigned ah4[4], al4[4];
                ldsm4(ah4, aOffH + ks * 32);
                ldsm4(al4, aOffL + ks * 32);
#pragma unroll
                for (int np = 0; np < 4; ++np) {
                    unsigned bh4[4], bl4[4];
                    uint32_t bo = (uint32_t)(np * 16640 + c * 128 + ks * 32);
                    ldsm4(bh4, bOffH + bo);
                    ldsm4(bl4, bOffL + bo);
                    mma_bf16(d[2*np],   ah4, bh4 + 0);
                    mma_bf16(d[2*np+1], ah4, bh4 + 2);
                    mma_bf16(d[2*np],   ah4, bl4 + 0);
                    mma_bf16(d[2*np+1], ah4, bl4 + 2);
                    mma_bf16(d[2*np],   al4, bh4 + 0);
                    mma_bf16(d[2*np+1], al4, bh4 + 2);
                }
            }
            __syncthreads();
        }

        // ---- fused epilogue ----
        float* __restrict__ hout = g_h[(t + 1) & 1];
#pragma unroll
        for (int rr = 0; rr < 2; ++rr) {
            const int Rg = m0 + rbase + rr * 8;
#pragma unroll
            for (int hh = 0; hh < 2; ++hh) {
                const int cb = ch0 + hh * 8 + 2 * tc;
                const float* xp = &g_xw[((size_t)t * BB + Rg) * G4 + cb];
                float2 x0 = *(const float2*)&xp[0];
                float2 x1 = *(const float2*)&xp[512];
                float2 x2 = *(const float2*)&xp[1024];
                float2 x3 = *(const float2*)&xp[1536];
                float2 kv = *(const float2*)&g_kg[t * HH + cb];
                float hn[2];
#pragma unroll
                for (int cc = 0; cc < 2; ++cc) {
                    int s  = rr * 4 + hh * 2 + cc;
                    int ri = rr * 2 + cc;
                    float gi = d[0 + hh][ri] + (cc ? x0.y : x0.x);
                    float gf = d[2 + hh][ri] + (cc ? x1.y : x1.x);
                    float gg = d[4 + hh][ri] + (cc ? x2.y : x2.x);
                    float go = d[6 + hh][ri] + (cc ? x3.y : x3.x);
                    gi = 1.0f / (1.0f + __expf(-gi));
                    gf = 1.0f / (1.0f + __expf(-gf));
                    gg = tanhf(gg);
                    go = 1.0f / (1.0f + __expf(-go));
                    float ct = gf * cs[s] + gi * gg;
                    float ht = go * tanhf(ct);
                    float kg = cc ? kv.y : kv.x;
                    cs[s] = kg * ct + (1.0f - kg) * cs[s];
                    hn[cc] = kg * ht + (1.0f - kg) * hs[s];
                    hs[s] = hn[cc];
                }
                *(float2*)&hout[(size_t)Rg * HH + cb] = make_float2(hn[0], hn[1]);
            }
        }
        __syncthreads();

        // ---- per-m-group grid barrier over 32 blocks ----
        if (t < TT - 1) {
            if (tid == 0) {
                __threadfence();
                atomicAdd(bar, 1u);
                const unsigned tgt = (unsigned)(t + 1) * 32u;
                unsigned v;
                do {
                    asm volatile("ld.acquire.gpu.global.u32 %0, [%1];"
                                 : "=r"(v) : "l"(bar) : "memory");
                    if (v >= tgt) break;
                    __nanosleep(64);
                } while (true);
            }
            __syncthreads();
        }
    }
}

// ---------------------------------------------------------------------------
// Phase 3: head (logits + log_softmax). Final h in g_h[0] (T even).
// ---------------------------------------------------------------------------
__global__ void head_kernel(const float* __restrict__ fc_w,
                            const float* __restrict__ fc_b,
                            float* __restrict__ out) {
    __shared__ float hrow[HH];
    __shared__ float part[CC][4];
    __shared__ float logits[CC];
    __shared__ float s_lse;
    const int b = blockIdx.x;
    const int tid = threadIdx.x;   // 256

    *(float2*)&hrow[tid * 2] = *(const float2*)&g_h[0][(size_t)b * HH + tid * 2];
    __syncthreads();

    const int c = tid >> 2;
    const int s = tid & 3;
    if (c < CC) {
        float sum = 0.0f;
        const float* wp = &fc_w[(size_t)(s * 128) * CC + c];
        const float* hp = &hrow[s * 128];
#pragma unroll 16
        for (int k = 0; k < 128; ++k) sum += hp[k] * wp[k * CC];
        part[c][s] = sum;
    }
    __syncthreads();

    if (tid < CC)
        logits[tid] = part[tid][0] + part[tid][1] + part[tid][2] + part[tid][3] + fc_b[tid];
    __syncthreads();

    if (tid == 0) {
        float mx = -1e30f;
        for (int i = 0; i < CC; ++i) mx = fmaxf(mx, logits[i]);
        float sm = 0.0f;
        for (int i = 0; i < CC; ++i) sm += expf(logits[i] - mx);
        s_lse = mx + logf(sm);
    }
    __syncthreads();

    if (tid < CC) out[(size_t)b * CC + tid] = logits[tid] - s_lse;
}

// ---------------------------------------------------------------------------
// Launch
// ---------------------------------------------------------------------------
extern "C" void kernel_launch(void* const* d_in, const int* in_sizes, int n_in,
                              void* d_out, int out_size) {
    const float* x     = (const float*)d_in[0];
    const float* Wx    = (const float*)d_in[1];
    const float* Wh    = (const float*)d_in[2];
    const float* bias  = (const float*)d_in[3];
    const float* tau   = (const float*)d_in[4];
    const float* shift = (const float*)d_in[5];
    const float* fc_w  = (const float*)d_in[6];
    const float* fc_b  = (const float*)d_in[7];
    float* out = (float*)d_out;

    cudaFuncSetAttribute(plstm_mma,
                         cudaFuncAttributeMaxDynamicSharedMemorySize, SMEM_TOTAL);

    zero_state<<<512, 256>>>();
    kg_kernel<<<512, 256>>>(tau, shift);

    dim3 g1(G4 / 128, (TT * BB) / 128);   // (16, 512)
    xw_gemm<<<g1, 256>>>(x, Wx, bias);

    dim3 g2(32, 2);                        // 64 persistent blocks
    plstm_mma<<<g2, 256, SMEM_TOTAL>>>(Wh);

    head_kernel<<<BB, 256>>>(fc_w, fc_b, out);
}

// round 13
// speedup vs baseline: 1.6882x; 1.3771x over previous
#include <cuda_runtime.h>
#include <cuda_bf16.h>
#include <math.h>
#include <stdint.h>

// Problem constants
#define BB 256
#define PP 5
#define TT 256
#define FF 128
#define HH 512
#define CC 60
#define DD 640      // P*F
#define G4 2048     // 4*H

// Scratch (device globals: allocation-free per harness rules)
__device__ float g_xw[134217728ULL];             // (T*B) x [ch*4+gate] fp32 (permuted)
__device__ float g_h[BB * HH];                   // final h fp32 (for head)
__device__ __nv_bfloat16 g_hbf[2][2][BB][HH];    // [buf][plane hi/lo][row][ch]
__device__ float g_kg[TT * HH];                  // time gate k(t,ch)
__device__ unsigned g_bar4[4];                   // per-m-group barrier counters

// ---------------------------------------------------------------------------
// FFMA2 helper (xw_gemm only)
// ---------------------------------------------------------------------------
__device__ __forceinline__ float2 ffma2(float2 a, float2 b, float2 c) {
    unsigned long long ua = *reinterpret_cast<unsigned long long*>(&a);
    unsigned long long ub = *reinterpret_cast<unsigned long long*>(&b);
    unsigned long long uc = *reinterpret_cast<unsigned long long*>(&c);
    unsigned long long ud;
    asm("fma.rn.f32x2 %0, %1, %2, %3;" : "=l"(ud) : "l"(ua), "l"(ub), "l"(uc));
    return *reinterpret_cast<float2*>(&ud);
}

// ---------------------------------------------------------------------------
// Warp-level MMA helpers (HMMA SASS; proven in R12)
// ---------------------------------------------------------------------------
__device__ __forceinline__ void ldsm4(unsigned* r, uint32_t addr) {
    asm volatile("ldmatrix.sync.aligned.m8n8.x4.shared.b16 {%0, %1, %2, %3}, [%4];"
                 : "=r"(r[0]), "=r"(r[1]), "=r"(r[2]), "=r"(r[3]) : "r"(addr));
}

__device__ __forceinline__ void mma_bf16(float* d, const unsigned* a, const unsigned* b) {
    asm volatile(
        "mma.sync.aligned.m16n8k16.row.col.f32.bf16.bf16.f32 "
        "{%0, %1, %2, %3}, {%4, %5, %6, %7}, {%8, %9}, {%0, %1, %2, %3};"
        : "+f"(d[0]), "+f"(d[1]), "+f"(d[2]), "+f"(d[3])
        : "r"(a[0]), "r"(a[1]), "r"(a[2]), "r"(a[3]), "r"(b[0]), "r"(b[1]));
}

// ---------------------------------------------------------------------------
// Init kernels
// ---------------------------------------------------------------------------
__global__ void zero_state() {
    int i = blockIdx.x * blockDim.x + threadIdx.x;
    if (i < 131072) ((float*)g_hbf)[i] = 0.0f;   // zero g_hbf[0] hi+lo planes
    if (i < 4) g_bar4[i] = 0u;
}

__global__ void kg_kernel(const float* __restrict__ tau,
                          const float* __restrict__ shift) {
    int i = blockIdx.x * blockDim.x + threadIdx.x;
    if (i < TT * HH) {
        int t = i >> 9, ch = i & 511;
        float tv = tau[ch], sv = shift[ch];
        float xph = ((float)t - sv) / tv;
        float phi = xph - floorf(xph);
        float kg = (phi < 0.025f) ? (40.0f * phi)
                 : (phi < 0.05f)  ? (2.0f - 40.0f * phi)
                                  : (0.001f * phi);
        g_kg[i] = kg;
    }
}

// ---------------------------------------------------------------------------
// Phase 1: XW GEMM (FFMA2). Epilogue stores PERMUTED: [row][ch*4+gate].
// ---------------------------------------------------------------------------
#define KT1 16
__global__ void __launch_bounds__(256, 2)
xw_gemm(const float* __restrict__ X, const float* __restrict__ Wx,
        const float* __restrict__ bvec) {
    __shared__ float a_s[2][KT1][130];
    __shared__ float b_s[2][KT1][128];

    const int tid = threadIdx.x;
    const int by  = blockIdx.y;
    const int n0  = blockIdx.x << 7;
    const int t   = by >> 1;
    const int bb0 = (by & 1) << 7;
    const int tx = tid & 15;
    const int ty = tid >> 4;
    const int lakk = tid & 15;
    const int lamm = tid >> 4;
    const int lbnn = tid & 127;
    const int lbk0 = (tid >> 7) << 3;

    float2 acc[8][4];
#pragma unroll
    for (int j = 0; j < 8; ++j)
#pragma unroll
        for (int p = 0; p < 4; ++p) acc[j][p] = make_float2(0.f, 0.f);

    float ra[8], rb[8];
    auto loadA = [&](int k0) {
        int p = k0 >> 7;
        int f = (k0 & 127) + lakk;
        size_t colofs = (size_t)p * (TT * FF) + (size_t)t * FF + f;
#pragma unroll
        for (int i = 0; i < 8; ++i)
            ra[i] = X[(size_t)(bb0 + lamm + 16 * i) * (PP * TT * FF) + colofs];
    };
    auto loadB = [&](int k0) {
#pragma unroll
        for (int i = 0; i < 8; ++i)
            rb[i] = Wx[(size_t)(k0 + lbk0 + i) * G4 + n0 + lbnn];
    };
    auto stsAB = [&](int buf) {
#pragma unroll
        for (int i = 0; i < 8; ++i) a_s[buf][lakk][lamm + 16 * i] = ra[i];
#pragma unroll
        for (int i = 0; i < 8; ++i) b_s[buf][lbk0 + i][lbnn] = rb[i];
    };

    const int NS = DD / KT1;
    loadA(0); loadB(0);
    stsAB(0);
    __syncthreads();

    for (int s = 0; s < NS; ++s) {
        const int buf = s & 1;
        if (s + 1 < NS) { loadA((s + 1) * KT1); loadB((s + 1) * KT1); }
#pragma unroll
        for (int kk = 0; kk < KT1; ++kk) {
            float2 a01 = *(const float2*)&a_s[buf][kk][ty * 8 + 0];
            float2 a23 = *(const float2*)&a_s[buf][kk][ty * 8 + 2];
            float2 a45 = *(const float2*)&a_s[buf][kk][ty * 8 + 4];
            float2 a67 = *(const float2*)&a_s[buf][kk][ty * 8 + 6];
#pragma unroll
            for (int j = 0; j < 8; ++j) {
                float bv = b_s[buf][kk][tx + 16 * j];
                float2 bb = make_float2(bv, bv);
                acc[j][0] = ffma2(a01, bb, acc[j][0]);
                acc[j][1] = ffma2(a23, bb, acc[j][1]);
                acc[j][2] = ffma2(a45, bb, acc[j][2]);
                acc[j][3] = ffma2(a67, bb, acc[j][3]);
            }
        }
        if (s + 1 < NS) stsAB(buf ^ 1);
        __syncthreads();
    }

    const int mrow = by * 128 + ty * 8;
#pragma unroll
    for (int j = 0; j < 8; ++j) {
        int n = n0 + tx + 16 * j;
        float bn = bvec[n];
        int nperm = (n & 511) * 4 + (n >> 9);    // [ch*4+gate]
#pragma unroll
        for (int p = 0; p < 4; ++p) {
            size_t o = (size_t)(mrow + 2 * p) * G4 + nperm;
            g_xw[o]      = acc[j][p].x + bn;
            g_xw[o + G4] = acc[j][p].y + bn;
        }
    }
}

// ---------------------------------------------------------------------------
// Phase 2: PERSISTENT recurrence on mma.sync, v2.
//   Grid (32, 4) = 128 blocks (all SMs), 256 threads (8 warps).
//   Block: M=64 rows x N=64 cols (n = chl*4 + gate), K=512.
//   Warp (mt, nh): m16 tile mt, channel half nh (8 ch = 4 n8 tiles).
//   Split-bf16 D = Ahi*Bhi + Ahi*Blo + Alo*Bhi (fp32 acc).
//   h lives in gmem as bf16 hi/lo planes -> A staging is LDG+STS only.
//   A double-buffered 128-K chunks: 4 chunks, 4 syncs/step.
// ---------------------------------------------------------------------------
#define APITCH 272                       // bytes per A row (128 bf16 + pad)
#define ABUFP  17408                     // A plane stride (64*272)
#define ABUFB  34816                     // A buffer stride (2 planes)
#define BPITCH 1040                      // bytes per B row (512 bf16 + pad)
#define SM_B   0
#define SM_BL  66560                     // 64*1040
#define SM_A   133120
#define SMEM_TOTAL 202752                // + 2*34816

__global__ void __launch_bounds__(256, 1)
plstm_mma(const float* __restrict__ Wh) {
    extern __shared__ char smc[];
    const uint32_t sb = (uint32_t)__cvta_generic_to_shared(smc);
    const int tid  = threadIdx.x;
    const int wid  = tid >> 5;
    const int lane = tid & 31;
    const int ng   = blockIdx.x;          // 0..31 channel tile (16 ch)
    const int mg   = blockIdx.y;          // 0..3  row group (64 rows)
    const int m0   = mg << 6;
    const int ch0  = ng << 4;
    const int mt   = wid & 3;             // m16 tile
    const int nh   = wid >> 2;            // channel half (8 ch)

    // ---- prologue: Wh -> smem BT[n][k] hi/lo, n = chl*4 + gate ----
    {
        const int n   = tid >> 2;                 // 0..63
        const int kq  = (tid & 3) * 128;
        const int chl = n >> 2;
        const int gt  = n & 3;
        const float* wp = &Wh[(size_t)kq * G4 + gt * HH + ch0 + chl];
        char* bh = smc + SM_B  + n * BPITCH + kq * 2;
        char* bl = smc + SM_BL + n * BPITCH + kq * 2;
        for (int k = 0; k < 128; ++k) {
            float wv = wp[(size_t)k * G4];
            __nv_bfloat16 hi = __float2bfloat16(wv);
            __nv_bfloat16 lo = __float2bfloat16(wv - __bfloat162float(hi));
            *(__nv_bfloat16*)(bh + k * 2) = hi;
            *(__nv_bfloat16*)(bl + k * 2) = lo;
        }
    }
    __syncthreads();

    // ldmatrix address precompute (R12-proven patterns)
    const int a_row = mt * 16 + (lane & 7) + ((lane >> 3) & 1) * 8;
    const uint32_t aH = sb + SM_A + a_row * APITCH + ((lane >> 4) & 1) * 16;
    const int b_row = (lane & 7) + ((lane >> 4) & 1) * 8;
    const uint32_t bH = sb + SM_B  + (nh * 32 + b_row) * BPITCH + ((lane >> 3) & 1) * 16;
    const uint32_t bL = sb + SM_BL + (nh * 32 + b_row) * BPITCH + ((lane >> 3) & 1) * 16;

    // A staging mapping: thread -> (row, plane, k-half)
    const int sr = tid & 63;
    const int sp = tid >> 7;              // plane
    const int skh = ((tid >> 6) & 1) * 64; // k offset within 128-chunk

    // epilogue mapping
    const int gr = lane >> 2;
    const int tc = lane & 3;
    const int row = m0 + mt * 16 + gr + (tc & 1) * 8;

    float cs[4], hs[4];
#pragma unroll
    for (int j = 0; j < 4; ++j) { cs[j] = 0.f; hs[j] = 0.f; }

    unsigned* bar = &g_bar4[mg];
    uint4 pf[8];

    for (int t = 0; t < TT; ++t) {
        const int hb = t & 1;

        float d[4][4];
#pragma unroll
        for (int j = 0; j < 4; ++j)
#pragma unroll
            for (int q = 0; q < 4; ++q) d[j][q] = 0.f;

        // stage chunk 0
        {
            const __nv_bfloat16* hp = &g_hbf[hb][sp][m0 + sr][skh];
#pragma unroll
            for (int j = 0; j < 8; ++j) pf[j] = ((const uint4*)hp)[j];
            char* dst = smc + SM_A + sp * ABUFP + sr * APITCH + skh * 2;
#pragma unroll
            for (int j = 0; j < 8; ++j) *(uint4*)(dst + j * 16) = pf[j];
        }
        __syncthreads();

        for (int c = 0; c < 4; ++c) {
            const int buf = c & 1;
            // prefetch next chunk (regs) while MMA runs
            if (c < 3) {
                const __nv_bfloat16* hp = &g_hbf[hb][sp][m0 + sr][(c + 1) * 128 + skh];
#pragma unroll
                for (int j = 0; j < 8; ++j) pf[j] = ((const uint4*)hp)[j];
            }

            // MMA over this 128-K chunk: 8 k16 steps
#pragma unroll
            for (int ks = 0; ks < 8; ++ks) {
                unsigned ah4[4], al4[4];
                ldsm4(ah4, aH + buf * ABUFB + ks * 32);
                ldsm4(al4, aH + buf * ABUFB + ABUFP + ks * 32);
#pragma unroll
                for (int np2 = 0; np2 < 2; ++np2) {
                    unsigned bh4[4], bl4[4];
                    uint32_t bo = (uint32_t)(np2 * 16640 + c * 256 + ks * 32);
                    ldsm4(bh4, bH + bo);
                    ldsm4(bl4, bL + bo);
                    mma_bf16(d[np2 * 2],     ah4, bh4 + 0);
                    mma_bf16(d[np2 * 2 + 1], ah4, bh4 + 2);
                    mma_bf16(d[np2 * 2],     ah4, bl4 + 0);
                    mma_bf16(d[np2 * 2 + 1], ah4, bl4 + 2);
                    mma_bf16(d[np2 * 2],     al4, bh4 + 0);
                    mma_bf16(d[np2 * 2 + 1], al4, bh4 + 2);
                }
            }

            if (c < 3) {
                char* dst = smc + SM_A + (buf ^ 1) * ABUFB + sp * ABUFP + sr * APITCH + skh * 2;
#pragma unroll
                for (int j = 0; j < 8; ++j) *(uint4*)(dst + j * 16) = pf[j];
                __syncthreads();
            }
        }

        // ---- fused epilogue: gate regroup (shfl), gates, time gate, update ----
        const int nb = (t + 1) & 1;
#pragma unroll
        for (int dq = 0; dq < 4; ++dq) {
            float s0 = __shfl_xor_sync(0xffffffffu, (tc & 1) ? d[dq][0] : d[dq][2], 1);
            float s1 = __shfl_xor_sync(0xffffffffu, (tc & 1) ? d[dq][1] : d[dq][3], 1);
            float gi, gf, gg, go;
            if (tc & 1) { gi = s0;      gf = s1;      gg = d[dq][2]; go = d[dq][3]; }
            else        { gi = d[dq][0]; gf = d[dq][1]; gg = s0;     go = s1; }
            const int ch = ch0 + nh * 8 + dq * 2 + (tc >> 1);
            float4 xw = *(const float4*)&g_xw[((size_t)t * BB + row) * G4 + ch * 4];
            float kg = g_kg[t * HH + ch];
            gi += xw.x; gf += xw.y; gg += xw.z; go += xw.w;
            gi = 1.0f / (1.0f + __expf(-gi));
            gf = 1.0f / (1.0f + __expf(-gf));
            gg = tanhf(gg);
            go = 1.0f / (1.0f + __expf(-go));
            float ct = gf * cs[dq] + gi * gg;
            float ht = go * tanhf(ct);
            cs[dq] = kg * ct + (1.0f - kg) * cs[dq];
            float hn = kg * ht + (1.0f - kg) * hs[dq];
            hs[dq] = hn;
            __nv_bfloat16 hi = __float2bfloat16(hn);
            __nv_bfloat16 lo = __float2bfloat16(hn - __bfloat162float(hi));
            g_hbf[nb][0][row][ch] = hi;
            g_hbf[nb][1][row][ch] = lo;
            if (t == TT - 1) g_h[(size_t)row * HH + ch] = hn;
        }
        __syncthreads();

        // ---- per-m-group grid barrier over 32 blocks ----
        if (t < TT - 1) {
            if (tid == 0) {
                __threadfence();
                atomicAdd(bar, 1u);
                const unsigned tgt = (unsigned)(t + 1) * 32u;
                unsigned v;
                do {
                    asm volatile("ld.acquire.gpu.global.u32 %0, [%1];"
                                 : "=r"(v) : "l"(bar) : "memory");
                    if (v >= tgt) break;
                    __nanosleep(64);
                } while (true);
            }
            __syncthreads();
        }
    }
}

// ---------------------------------------------------------------------------
// Phase 3: head (logits + log_softmax)
// ---------------------------------------------------------------------------
__global__ void head_kernel(const float* __restrict__ fc_w,
                            const float* __restrict__ fc_b,
                            float* __restrict__ out) {
    __shared__ float hrow[HH];
    __shared__ float part[CC][4];
    __shared__ float logits[CC];
    __shared__ float s_lse;
    const int b = blockIdx.x;
    const int tid = threadIdx.x;   // 256

    *(float2*)&hrow[tid * 2] = *(const float2*)&g_h[(size_t)b * HH + tid * 2];
    __syncthreads();

    const int c = tid >> 2;
    const int s = tid & 3;
    if (c < CC) {
        float sum = 0.0f;
        const float* wp = &fc_w[(size_t)(s * 128) * CC + c];
        const float* hp = &hrow[s * 128];
#pragma unroll 16
        for (int k = 0; k < 128; ++k) sum += hp[k] * wp[k * CC];
        part[c][s] = sum;
    }
    __syncthreads();

    if (tid < CC)
        logits[tid] = part[tid][0] + part[tid][1] + part[tid][2] + part[tid][3] + fc_b[tid];
    __syncthreads();

    if (tid == 0) {
        float mx = -1e30f;
        for (int i = 0; i < CC; ++i) mx = fmaxf(mx, logits[i]);
        float sm = 0.0f;
        for (int i = 0; i < CC; ++i) sm += expf(logits[i] - mx);
        s_lse = mx + logf(sm);
    }
    __syncthreads();

    if (tid < CC) out[(size_t)b * CC + tid] = logits[tid] - s_lse;
}

// ---------------------------------------------------------------------------
// Launch
// ---------------------------------------------------------------------------
extern "C" void kernel_launch(void* const* d_in, const int* in_sizes, int n_in,
                              void* d_out, int out_size) {
    const float* x     = (const float*)d_in[0];
    const float* Wx    = (const float*)d_in[1];
    const float* Wh    = (const float*)d_in[2];
    const float* bias  = (const float*)d_in[3];
    const float* tau   = (const float*)d_in[4];
    const float* shift = (const float*)d_in[5];
    const float* fc_w  = (const float*)d_in[6];
    const float* fc_b  = (const float*)d_in[7];
    float* out = (float*)d_out;

    cudaFuncSetAttribute(plstm_mma,
                         cudaFuncAttributeMaxDynamicSharedMemorySize, SMEM_TOTAL);

    zero_state<<<512, 256>>>();
    kg_kernel<<<512, 256>>>(tau, shift);

    dim3 g1(G4 / 128, (TT * BB) / 128);   // (16, 512)
    xw_gemm<<<g1, 256>>>(x, Wx, bias);

    dim3 g2(32, 4);                        // 128 persistent blocks
    plstm_mma<<<g2, 256, SMEM_TOTAL>>>(Wh);

    head_kernel<<<BB, 256>>>(fc_w, fc_b, out);
}

// round 14
// speedup vs baseline: 2.7531x; 1.6308x over previous
#include <cuda_runtime.h>
#include <cuda_fp16.h>
#include <math.h>
#include <stdint.h>

// Problem constants
#define BB 256
#define PP 5
#define TT 256
#define FF 128
#define HH 512
#define CC 60
#define DD 640      // P*F
#define G4 2048     // 4*H
#define MM 65536    // T*B rows

// Scratch (device globals: allocation-free per harness rules)
__device__ float g_xw[134217728ULL];           // (T*B) x [ch*4+gate] fp32
__device__ __half g_xh[2][(size_t)MM * DD];    // x planes hi/lo, [m][k]
__device__ __half g_wh[(size_t)G4 * DD];       // Wx fp16, [n'][k], n'=ch*4+gate
__device__ float g_bp[G4];                     // permuted bias
__device__ float g_h[BB * HH];                 // final h fp32 (for head)
__device__ __half g_hh[2][2][BB][HH];          // [buf][plane hi/lo][row][ch]
__device__ float g_kg[TT * HH];                // time gate k(t,ch)
__device__ unsigned g_bar4[4];                 // per-m-group barrier counters

// ---------------------------------------------------------------------------
// MMA helpers (HMMA SASS; fragment patterns proven in R12/R13)
// ---------------------------------------------------------------------------
__device__ __forceinline__ void ldsm4(unsigned* r, uint32_t addr) {
    asm volatile("ldmatrix.sync.aligned.m8n8.x4.shared.b16 {%0, %1, %2, %3}, [%4];"
                 : "=r"(r[0]), "=r"(r[1]), "=r"(r[2]), "=r"(r[3]) : "r"(addr));
}

__device__ __forceinline__ void mma_fp16(float* d, const unsigned* a, const unsigned* b) {
    asm volatile(
        "mma.sync.aligned.m16n8k16.row.col.f32.f16.f16.f32 "
        "{%0, %1, %2, %3}, {%4, %5, %6, %7}, {%8, %9}, {%0, %1, %2, %3};"
        : "+f"(d[0]), "+f"(d[1]), "+f"(d[2]), "+f"(d[3])
        : "r"(a[0]), "r"(a[1]), "r"(a[2]), "r"(a[3]), "r"(b[0]), "r"(b[1]));
}

// ---------------------------------------------------------------------------
// Init / prep kernels
// ---------------------------------------------------------------------------
__global__ void zero_state() {
    int i = blockIdx.x * blockDim.x + threadIdx.x;
    if (i < 131072) ((float*)g_hh)[i] = 0.0f;   // zero g_hh[0] both planes (+[1] partially, harmless)
    if (i < 4) g_bar4[i] = 0u;
}

__global__ void kg_kernel(const float* __restrict__ tau,
                          const float* __restrict__ shift) {
    int i = blockIdx.x * blockDim.x + threadIdx.x;
    if (i < TT * HH) {
        int t = i >> 9, ch = i & 511;
        float tv = tau[ch], sv = shift[ch];
        float xph = ((float)t - sv) / tv;
        float phi = xph - floorf(xph);
        float kg = (phi < 0.025f) ? (40.0f * phi)
                 : (phi < 0.05f)  ? (2.0f - 40.0f * phi)
                                  : (0.001f * phi);
        g_kg[i] = kg;
    }
}

// X (B,P,T,F) fp32 -> g_xh planes [m][k], m = t*256+b, k = p*128+f
__global__ void xprep(const float* __restrict__ X) {
    size_t idx = (size_t)blockIdx.x * blockDim.x + threadIdx.x;
    if (idx >= (size_t)MM * 160) return;
    int m  = (int)(idx / 160);
    int kq = (int)(idx % 160) * 4;
    int t = m >> 8, b = m & 255;
    int p = kq >> 7, f = kq & 127;
    float4 v = *(const float4*)&X[(((size_t)b * PP + p) * TT + t) * FF + f];
    __half h0 = __float2half(v.x), h1 = __float2half(v.y);
    __half h2 = __float2half(v.z), h3 = __float2half(v.w);
    __half l0 = __float2half(v.x - __half2float(h0));
    __half l1 = __float2half(v.y - __half2float(h1));
    __half l2 = __float2half(v.z - __half2float(h2));
    __half l3 = __float2half(v.w - __half2float(h3));
    __half hi4[4] = {h0, h1, h2, h3};
    __half lo4[4] = {l0, l1, l2, l3};
    *(uint2*)&g_xh[0][(size_t)m * DD + kq] = *(uint2*)hi4;
    *(uint2*)&g_xh[1][(size_t)m * DD + kq] = *(uint2*)lo4;
}

// Wx [k][4H] fp32 -> g_wh [n'][k] fp16, n' = ch*4 + gate (wcol = gate*512+ch)
__global__ void wprep(const float* __restrict__ Wx, const float* __restrict__ bvec) {
    int idx = blockIdx.x * blockDim.x + threadIdx.x;
    if (idx >= G4 * 160) return;
    int np = idx / 160;
    int kq = (idx % 160) * 4;
    int gate = np & 3, ch = np >> 2;
    int wcol = gate * HH + ch;
    __half h4[4];
#pragma unroll
    for (int j = 0; j < 4; ++j)
        h4[j] = __float2half(Wx[(size_t)(kq + j) * G4 + wcol]);
    *(uint2*)&g_wh[(size_t)np * DD + kq] = *(uint2*)h4;
    if (kq == 0) g_bp[np] = bvec[wcol];
}

// ---------------------------------------------------------------------------
// Phase 1: XW GEMM on mma.sync. C[m][n'] = Xsplit @ Whalf + bias.
//   Tile M128 x N128, K=640 (40 k16 stages, double buffered).
//   Warp (mw = wid&3 -> m32, nw = wid>>2 -> n64). 2 products (Ahi,Alo)*B.
// ---------------------------------------------------------------------------
#define XSM_A 0          // A: [buf][plane][128 rows][48B]
#define XSM_B 24576      // B: [buf][128 rows][48B]
#define XSM_TOT 36864

__global__ void __launch_bounds__(256, 2)
xw_mma(int dummy) {
    extern __shared__ char smc[];
    const uint32_t sb = (uint32_t)__cvta_generic_to_shared(smc);
    const int tid  = threadIdx.x;
    const int wid  = tid >> 5;
    const int lane = tid & 31;
    const int n0   = blockIdx.x << 7;
    const int m0   = blockIdx.y << 7;
    const int mw   = wid & 3;
    const int nw   = wid >> 2;

    // ldsm addresses
    const int a_row = mw * 32 + (lane & 7) + ((lane >> 3) & 1) * 8;
    const uint32_t aOff = sb + XSM_A + a_row * 48 + ((lane >> 4) & 1) * 16;
    const int b_row = (lane & 7) + ((lane >> 4) & 1) * 8;
    const uint32_t bOff = sb + XSM_B + (nw * 64 + b_row) * 48 + ((lane >> 3) & 1) * 16;

    // staging maps
    const int arow = tid & 127;
    const int apl  = tid >> 7;
    const int brow = tid >> 1;
    const int bhf  = tid & 1;

    float d[2][8][4];
#pragma unroll
    for (int i = 0; i < 2; ++i)
#pragma unroll
        for (int j = 0; j < 8; ++j)
#pragma unroll
            for (int q = 0; q < 4; ++q) d[i][j][q] = 0.f;

    uint4 pa0, pa1, pb;
    auto ldg = [&](int k0) {
        const __half* ap = &g_xh[apl][(size_t)(m0 + arow) * DD + k0];
        pa0 = ((const uint4*)ap)[0];
        pa1 = ((const uint4*)ap)[1];
        pb  = *(const uint4*)&g_wh[(size_t)(n0 + brow) * DD + k0 + bhf * 8];
    };
    auto sts = [&](int buf) {
        char* ad = smc + XSM_A + buf * 12288 + apl * 6144 + arow * 48;
        ((uint4*)ad)[0] = pa0;
        ((uint4*)ad)[1] = pa1;
        *(uint4*)(smc + XSM_B + buf * 6144 + brow * 48 + bhf * 16) = pb;
    };

    ldg(0);
    sts(0);
    __syncthreads();

    for (int s = 0; s < 40; ++s) {
        const int buf = s & 1;
        if (s < 39) ldg((s + 1) * 16);

        unsigned bq[4][4];
#pragma unroll
        for (int p4 = 0; p4 < 4; ++p4)
            ldsm4(bq[p4], bOff + buf * 6144 + p4 * 16 * 48);
#pragma unroll
        for (int mt = 0; mt < 2; ++mt) {
            unsigned ah[4], al[4];
            ldsm4(ah, aOff + buf * 12288 + mt * 16 * 48);
            ldsm4(al, aOff + buf * 12288 + 6144 + mt * 16 * 48);
#pragma unroll
            for (int p4 = 0; p4 < 4; ++p4) {
                mma_fp16(d[mt][2 * p4],     ah, bq[p4] + 0);
                mma_fp16(d[mt][2 * p4 + 1], ah, bq[p4] + 2);
                mma_fp16(d[mt][2 * p4],     al, bq[p4] + 0);
                mma_fp16(d[mt][2 * p4 + 1], al, bq[p4] + 2);
            }
        }
        if (s < 39) sts(buf ^ 1);
        __syncthreads();
    }

    // epilogue: bias + store fp32
    const int gr = lane >> 2;
    const int tc = lane & 3;
#pragma unroll
    for (int mt = 0; mt < 2; ++mt) {
        const int r0 = m0 + mw * 32 + mt * 16 + gr;
#pragma unroll
        for (int n8 = 0; n8 < 8; ++n8) {
            const int col = n0 + nw * 64 + n8 * 8 + tc * 2;
            float2 bs = *(const float2*)&g_bp[col];
            *(float2*)&g_xw[(size_t)r0 * G4 + col] =
                make_float2(d[mt][n8][0] + bs.x, d[mt][n8][1] + bs.y);
            *(float2*)&g_xw[(size_t)(r0 + 8) * G4 + col] =
                make_float2(d[mt][n8][2] + bs.x, d[mt][n8][3] + bs.y);
        }
    }
}

// ---------------------------------------------------------------------------
// Phase 2: PERSISTENT recurrence on mma.sync, fp16 2-product.
//   Grid (32, 4) = 128 blocks, 256 threads (8 warps).
//   Block: M=64 rows x N=64 cols (n = chl*4 + gate), K=512.
//   D = Ahi*B + Alo*B (B = Wh single fp16 plane; A = h split hi/lo fp16).
//   Wh resident in smem all steps; A double-buffered 128-K chunks.
// ---------------------------------------------------------------------------
#define APITCH 272                       // bytes per A row (128 fp16 + pad)
#define ABUFP  17408                     // A plane stride (64*272)
#define ABUFB  34816                     // A buffer stride (2 planes)
#define BPITCH 1040                      // bytes per B row (512 fp16 + pad)
#define SM_B   0
#define SM_A   66560                     // 64*1040
#define SMEM_TOTAL 136192                // + 2*34816

__global__ void __launch_bounds__(256, 1)
plstm_mma(const float* __restrict__ Wh) {
    extern __shared__ char smc[];
    const uint32_t sb = (uint32_t)__cvta_generic_to_shared(smc);
    const int tid  = threadIdx.x;
    const int wid  = tid >> 5;
    const int lane = tid & 31;
    const int ng   = blockIdx.x;          // 0..31 channel tile (16 ch)
    const int mg   = blockIdx.y;          // 0..3  row group (64 rows)
    const int m0   = mg << 6;
    const int ch0  = ng << 4;
    const int mt   = wid & 3;             // m16 tile
    const int nh   = wid >> 2;            // channel half (8 ch)

    // ---- prologue: Wh -> smem BT[n][k] fp16, n = chl*4 + gate ----
    {
        const int n   = tid >> 2;                 // 0..63
        const int kq  = (tid & 3) * 128;
        const int chl = n >> 2;
        const int gt  = n & 3;
        const float* wp = &Wh[(size_t)kq * G4 + gt * HH + ch0 + chl];
        char* bh = smc + SM_B + n * BPITCH + kq * 2;
        for (int k = 0; k < 128; ++k)
            *(__half*)(bh + k * 2) = __float2half(wp[(size_t)k * G4]);
    }
    __syncthreads();

    // ldsm addresses
    const int a_row = mt * 16 + (lane & 7) + ((lane >> 3) & 1) * 8;
    const uint32_t aH = sb + SM_A + a_row * APITCH + ((lane >> 4) & 1) * 16;
    const int b_row = (lane & 7) + ((lane >> 4) & 1) * 8;
    const uint32_t bH = sb + SM_B + (nh * 32 + b_row) * BPITCH + ((lane >> 3) & 1) * 16;

    // A staging: thread -> (row, plane, k-half)
    const int sr  = tid & 63;
    const int sp  = tid >> 7;
    const int skh = ((tid >> 6) & 1) * 64;

    // epilogue mapping
    const int gr = lane >> 2;
    const int tc = lane & 3;
    const int row = m0 + mt * 16 + gr + (tc & 1) * 8;

    float cs[4], hs[4];
#pragma unroll
    for (int j = 0; j < 4; ++j) { cs[j] = 0.f; hs[j] = 0.f; }

    unsigned* bar = &g_bar4[mg];
    uint4 pf[8];

    for (int t = 0; t < TT; ++t) {
        const int hb = t & 1;

        // prefetch xw + kg for this step (latency hides under MMA chunks)
        float4 xw_r[4];
        float  kg_r[4];
#pragma unroll
        for (int dq = 0; dq < 4; ++dq) {
            const int ch = ch0 + nh * 8 + dq * 2 + (tc >> 1);
            xw_r[dq] = *(const float4*)&g_xw[((size_t)t * BB + row) * G4 + ch * 4];
            kg_r[dq] = g_kg[t * HH + ch];
        }

        float d[4][4];
#pragma unroll
        for (int j = 0; j < 4; ++j)
#pragma unroll
            for (int q = 0; q < 4; ++q) d[j][q] = 0.f;

        // stage chunk 0
        {
            const __half* hp = &g_hh[hb][sp][m0 + sr][skh];
#pragma unroll
            for (int j = 0; j < 8; ++j) pf[j] = ((const uint4*)hp)[j];
            char* dst = smc + SM_A + sp * ABUFP + sr * APITCH + skh * 2;
#pragma unroll
            for (int j = 0; j < 8; ++j) *(uint4*)(dst + j * 16) = pf[j];
        }
        __syncthreads();

        for (int c = 0; c < 4; ++c) {
            const int buf = c & 1;
            if (c < 3) {
                const __half* hp = &g_hh[hb][sp][m0 + sr][(c + 1) * 128 + skh];
#pragma unroll
                for (int j = 0; j < 8; ++j) pf[j] = ((const uint4*)hp)[j];
            }

#pragma unroll
            for (int ks = 0; ks < 8; ++ks) {
                unsigned ah4[4], al4[4];
                ldsm4(ah4, aH + buf * ABUFB + ks * 32);
                ldsm4(al4, aH + buf * ABUFB + ABUFP + ks * 32);
#pragma unroll
                for (int np2 = 0; np2 < 2; ++np2) {
                    unsigned bh4[4];
                    uint32_t bo = (uint32_t)(np2 * 16640 + c * 256 + ks * 32);
                    ldsm4(bh4, bH + bo);
                    mma_fp16(d[np2 * 2],     ah4, bh4 + 0);
                    mma_fp16(d[np2 * 2 + 1], ah4, bh4 + 2);
                    mma_fp16(d[np2 * 2],     al4, bh4 + 0);
                    mma_fp16(d[np2 * 2 + 1], al4, bh4 + 2);
                }
            }

            if (c < 3) {
                char* dst = smc + SM_A + (buf ^ 1) * ABUFB + sp * ABUFP + sr * APITCH + skh * 2;
#pragma unroll
                for (int j = 0; j < 8; ++j) *(uint4*)(dst + j * 16) = pf[j];
                __syncthreads();
            }
        }

        // ---- fused epilogue: gate regroup (shfl), gates, time gate, update ----
        const int nb = (t + 1) & 1;
#pragma unroll
        for (int dq = 0; dq < 4; ++dq) {
            float s0 = __shfl_xor_sync(0xffffffffu, (tc & 1) ? d[dq][0] : d[dq][2], 1);
            float s1 = __shfl_xor_sync(0xffffffffu, (tc & 1) ? d[dq][1] : d[dq][3], 1);
            float gi, gf, gg, go;
            if (tc & 1) { gi = s0;       gf = s1;       gg = d[dq][2]; go = d[dq][3]; }
            else        { gi = d[dq][0]; gf = d[dq][1]; gg = s0;       go = s1; }
            const int ch = ch0 + nh * 8 + dq * 2 + (tc >> 1);
            float4 xw = xw_r[dq];
            float kg = kg_r[dq];
            gi += xw.x; gf += xw.y; gg += xw.z; go += xw.w;
            gi = 1.0f / (1.0f + __expf(-gi));
            gf = 1.0f / (1.0f + __expf(-gf));
            gg = tanhf(gg);
            go = 1.0f / (1.0f + __expf(-go));
            float ct = gf * cs[dq] + gi * gg;
            float ht = go * tanhf(ct);
            cs[dq] = kg * ct + (1.0f - kg) * cs[dq];
            float hn = kg * ht + (1.0f - kg) * hs[dq];
            hs[dq] = hn;
            __half hi = __float2half(hn);
            __half lo = __float2half(hn - __half2float(hi));
            g_hh[nb][0][row][ch] = hi;
            g_hh[nb][1][row][ch] = lo;
            if (t == TT - 1) g_h[(size_t)row * HH + ch] = hn;
        }
        __syncthreads();

        // ---- per-m-group grid barrier over 32 blocks (tight spin) ----
        if (t < TT - 1) {
            if (tid == 0) {
                __threadfence();
                atomicAdd(bar, 1u);
                const unsigned tgt = (unsigned)(t + 1) * 32u;
                unsigned v;
                do {
                    asm volatile("ld.acquire.gpu.global.u32 %0, [%1];"
                                 : "=r"(v) : "l"(bar) : "memory");
                } while (v < tgt);
            }
            __syncthreads();
        }
    }
}

// ---------------------------------------------------------------------------
// Phase 3: head (logits + log_softmax)
// ---------------------------------------------------------------------------
__global__ void head_kernel(const float* __restrict__ fc_w,
                            const float* __restrict__ fc_b,
                            float* __restrict__ out) {
    __shared__ float hrow[HH];
    __shared__ float part[CC][4];
    __shared__ float logits[CC];
    __shared__ float s_lse;
    const int b = blockIdx.x;
    const int tid = threadIdx.x;   // 256

    *(float2*)&hrow[tid * 2] = *(const float2*)&g_h[(size_t)b * HH + tid * 2];
    __syncthreads();

    const int c = tid >> 2;
    const int s = tid & 3;
    if (c < CC) {
        float sum = 0.0f;
        const float* wp = &fc_w[(size_t)(s * 128) * CC + c];
        const float* hp = &hrow[s * 128];
#pragma unroll 16
        for (int k = 0; k < 128; ++k) sum += hp[k] * wp[k * CC];
        part[c][s] = sum;
    }
    __syncthreads();

    if (tid < CC)
        logits[tid] = part[tid][0] + part[tid][1] + part[tid][2] + part[tid][3] + fc_b[tid];
    __syncthreads();

    if (tid == 0) {
        float mx = -1e30f;
        for (int i = 0; i < CC; ++i) mx = fmaxf(mx, logits[i]);
        float sm = 0.0f;
        for (int i = 0; i < CC; ++i) sm += expf(logits[i] - mx);
        s_lse = mx + logf(sm);
    }
    __syncthreads();

    if (tid < CC) out[(size_t)b * CC + tid] = logits[tid] - s_lse;
}

// ---------------------------------------------------------------------------
// Launch
// ---------------------------------------------------------------------------
extern "C" void kernel_launch(void* const* d_in, const int* in_sizes, int n_in,
                              void* d_out, int out_size) {
    const float* x     = (const float*)d_in[0];
    const float* Wx    = (const float*)d_in[1];
    const float* Wh    = (const float*)d_in[2];
    const float* bias  = (const float*)d_in[3];
    const float* tau   = (const float*)d_in[4];
    const float* shift = (const float*)d_in[5];
    const float* fc_w  = (const float*)d_in[6];
    const float* fc_b  = (const float*)d_in[7];
    float* out = (float*)d_out;

    cudaFuncSetAttribute(xw_mma,
                         cudaFuncAttributeMaxDynamicSharedMemorySize, XSM_TOT);
    cudaFuncSetAttribute(plstm_mma,
                         cudaFuncAttributeMaxDynamicSharedMemorySize, SMEM_TOTAL);

    zero_state<<<512, 256>>>();
    kg_kernel<<<512, 256>>>(tau, shift);
    xprep<<<(int)(((size_t)MM * 160 + 255) / 256), 256>>>(x);
    wprep<<<(G4 * 160 + 255) / 256, 256>>>(Wx, bias);

    dim3 g1(G4 / 128, MM / 128);          // (16, 512)
    xw_mma<<<g1, 256, XSM_TOT>>>(0);

    dim3 g2(32, 4);                        // 128 persistent blocks
    plstm_mma<<<g2, 256, SMEM_TOTAL>>>(Wh);

    head_kernel<<<BB, 256>>>(fc_w, fc_b, out);
}

// round 15
// speedup vs baseline: 3.9514x; 1.4352x over previous
#include <cuda_runtime.h>
#include <cuda_fp16.h>
#include <math.h>
#include <stdint.h>

// Problem constants
#define BB 256
#define PP 5
#define TT 256
#define FF 128
#define HH 512
#define CC 60
#define DD 640      // P*F
#define G4 2048     // 4*H
#define MM 65536    // T*B rows

// Scratch (device globals: allocation-free per harness rules)
__device__ float g_xw[134217728ULL];           // (T*B) x [ch*4+gate] fp32
__device__ __half g_xh[(size_t)MM * DD];       // x fp16, [m][k]
__device__ __half g_wh[(size_t)G4 * DD];       // Wx fp16, [n'][k], n'=ch*4+gate
__device__ float g_bp[G4];                     // permuted bias
__device__ float g_h[BB * HH];                 // final h fp32 (for head)
__device__ __half g_hh[2][BB][HH];             // [buf][row][ch] fp16 h
__device__ float g_kg[TT * HH];                // time gate k(t,ch)
__device__ unsigned g_bar4[4];                 // per-m-group barrier counters

// ---------------------------------------------------------------------------
// MMA helpers (HMMA SASS; fragment patterns proven in R12-R14)
// ---------------------------------------------------------------------------
__device__ __forceinline__ void ldsm4(unsigned* r, uint32_t addr) {
    asm volatile("ldmatrix.sync.aligned.m8n8.x4.shared.b16 {%0, %1, %2, %3}, [%4];"
                 : "=r"(r[0]), "=r"(r[1]), "=r"(r[2]), "=r"(r[3]) : "r"(addr));
}

__device__ __forceinline__ void mma_fp16(float* d, const unsigned* a, const unsigned* b) {
    asm volatile(
        "mma.sync.aligned.m16n8k16.row.col.f32.f16.f16.f32 "
        "{%0, %1, %2, %3}, {%4, %5, %6, %7}, {%8, %9}, {%0, %1, %2, %3};"
        : "+f"(d[0]), "+f"(d[1]), "+f"(d[2]), "+f"(d[3])
        : "r"(a[0]), "r"(a[1]), "r"(a[2]), "r"(a[3]), "r"(b[0]), "r"(b[1]));
}

// ---------------------------------------------------------------------------
// Init / prep kernels
// ---------------------------------------------------------------------------
__global__ void zero_state() {
    int i = blockIdx.x * blockDim.x + threadIdx.x;
    if (i < 65536) ((float*)g_hh)[i] = 0.0f;   // zero g_hh[0] (256*512 fp16)
    if (i < 4) g_bar4[i] = 0u;
}

__global__ void kg_kernel(const float* __restrict__ tau,
                          const float* __restrict__ shift) {
    int i = blockIdx.x * blockDim.x + threadIdx.x;
    if (i < TT * HH) {
        int t = i >> 9, ch = i & 511;
        float tv = tau[ch], sv = shift[ch];
        float xph = ((float)t - sv) / tv;
        float phi = xph - floorf(xph);
        float kg = (phi < 0.025f) ? (40.0f * phi)
                 : (phi < 0.05f)  ? (2.0f - 40.0f * phi)
                                  : (0.001f * phi);
        g_kg[i] = kg;
    }
}

// X (B,P,T,F) fp32 -> g_xh [m][k] fp16, m = t*256+b, k = p*128+f
__global__ void xprep(const float* __restrict__ X) {
    size_t idx = (size_t)blockIdx.x * blockDim.x + threadIdx.x;
    if (idx >= (size_t)MM * 160) return;
    int m  = (int)(idx / 160);
    int kq = (int)(idx % 160) * 4;
    int t = m >> 8, b = m & 255;
    int p = kq >> 7, f = kq & 127;
    float4 v = *(const float4*)&X[(((size_t)b * PP + p) * TT + t) * FF + f];
    __half h4[4] = {__float2half(v.x), __float2half(v.y),
                    __float2half(v.z), __float2half(v.w)};
    *(uint2*)&g_xh[(size_t)m * DD + kq] = *(uint2*)h4;
}

// Wx [k][4H] fp32 -> g_wh [n'][k] fp16, n' = ch*4 + gate (wcol = gate*512+ch)
__global__ void wprep(const float* __restrict__ Wx, const float* __restrict__ bvec) {
    int idx = blockIdx.x * blockDim.x + threadIdx.x;
    if (idx >= G4 * 160) return;
    int np = idx / 160;
    int kq = (idx % 160) * 4;
    int gate = np & 3, ch = np >> 2;
    int wcol = gate * HH + ch;
    __half h4[4];
#pragma unroll
    for (int j = 0; j < 4; ++j)
        h4[j] = __float2half(Wx[(size_t)(kq + j) * G4 + wcol]);
    *(uint2*)&g_wh[(size_t)np * DD + kq] = *(uint2*)h4;
    if (kq == 0) g_bp[np] = bvec[wcol];
}

// ---------------------------------------------------------------------------
// Phase 1: XW GEMM on mma.sync, single fp16 product.
//   Tile M128 x N128, K=640 (40 k16 stages, double buffered).
//   Warp (mw = wid&3 -> m32, nw = wid>>2 -> n64).
// ---------------------------------------------------------------------------
#define XSM_A 0          // A: [buf][128 rows][48B]
#define XSM_B 12288      // B: [buf][128 rows][48B]
#define XSM_TOT 24576

__global__ void __launch_bounds__(256, 2)
xw_mma(int dummy) {
    extern __shared__ char smc[];
    const uint32_t sb = (uint32_t)__cvta_generic_to_shared(smc);
    const int tid  = threadIdx.x;
    const int wid  = tid >> 5;
    const int lane = tid & 31;
    const int n0   = blockIdx.x << 7;
    const int m0   = blockIdx.y << 7;
    const int mw   = wid & 3;
    const int nw   = wid >> 2;

    // ldsm addresses
    const int a_row = mw * 32 + (lane & 7) + ((lane >> 3) & 1) * 8;
    const uint32_t aOff = sb + XSM_A + a_row * 48 + ((lane >> 4) & 1) * 16;
    const int b_row = (lane & 7) + ((lane >> 4) & 1) * 8;
    const uint32_t bOff = sb + XSM_B + (nw * 64 + b_row) * 48 + ((lane >> 3) & 1) * 16;

    // staging maps (each thread: 16B of A, 16B of B)
    const int arow = tid >> 1;
    const int ahf  = tid & 1;

    float d[2][8][4];
#pragma unroll
    for (int i = 0; i < 2; ++i)
#pragma unroll
        for (int j = 0; j < 8; ++j)
#pragma unroll
            for (int q = 0; q < 4; ++q) d[i][j][q] = 0.f;

    uint4 pa, pb;
    auto ldg = [&](int k0) {
        pa = *(const uint4*)&g_xh[(size_t)(m0 + arow) * DD + k0 + ahf * 8];
        pb = *(const uint4*)&g_wh[(size_t)(n0 + arow) * DD + k0 + ahf * 8];
    };
    auto sts = [&](int buf) {
        *(uint4*)(smc + XSM_A + buf * 6144 + arow * 48 + ahf * 16) = pa;
        *(uint4*)(smc + XSM_B + buf * 6144 + arow * 48 + ahf * 16) = pb;
    };

    ldg(0);
    sts(0);
    __syncthreads();

    for (int s = 0; s < 40; ++s) {
        const int buf = s & 1;
        if (s < 39) ldg((s + 1) * 16);

        unsigned bq[4][4];
#pragma unroll
        for (int p4 = 0; p4 < 4; ++p4)
            ldsm4(bq[p4], bOff + buf * 6144 + p4 * 16 * 48);
#pragma unroll
        for (int mt = 0; mt < 2; ++mt) {
            unsigned ah[4];
            ldsm4(ah, aOff + buf * 6144 + mt * 16 * 48);
#pragma unroll
            for (int p4 = 0; p4 < 4; ++p4) {
                mma_fp16(d[mt][2 * p4],     ah, bq[p4] + 0);
                mma_fp16(d[mt][2 * p4 + 1], ah, bq[p4] + 2);
            }
        }
        if (s < 39) sts(buf ^ 1);
        __syncthreads();
    }

    // epilogue: bias + store fp32
    const int gr = lane >> 2;
    const int tc = lane & 3;
#pragma unroll
    for (int mt = 0; mt < 2; ++mt) {
        const int r0 = m0 + mw * 32 + mt * 16 + gr;
#pragma unroll
        for (int n8 = 0; n8 < 8; ++n8) {
            const int col = n0 + nw * 64 + n8 * 8 + tc * 2;
            float2 bs = *(const float2*)&g_bp[col];
            *(float2*)&g_xw[(size_t)r0 * G4 + col] =
                make_float2(d[mt][n8][0] + bs.x, d[mt][n8][1] + bs.y);
            *(float2*)&g_xw[(size_t)(r0 + 8) * G4 + col] =
                make_float2(d[mt][n8][2] + bs.x, d[mt][n8][3] + bs.y);
        }
    }
}

// ---------------------------------------------------------------------------
// Phase 2: PERSISTENT recurrence on mma.sync, single fp16 product.
//   Grid (32, 4) = 128 blocks, 256 threads (8 warps).
//   Block: M=64 rows x N=64 cols (n = chl*4 + gate), K=512.
//   D = A*B (A = h fp16, B = Wh fp16; fp32 accumulate).
//   Wh resident in smem all steps; A double-buffered 256-K chunks (2 syncs).
// ---------------------------------------------------------------------------
#define APITCH 528                       // bytes per A row (256 fp16 + pad)
#define ABUF   33792                     // A buffer stride (64*528)
#define BPITCH 1040                      // bytes per B row (512 fp16 + pad)
#define SM_B   0
#define SM_A   66560                     // 64*1040
#define SMEM_TOTAL 134144                // + 2*33792

__global__ void __launch_bounds__(256, 1)
plstm_mma(const float* __restrict__ Wh) {
    extern __shared__ char smc[];
    const uint32_t sb = (uint32_t)__cvta_generic_to_shared(smc);
    const int tid  = threadIdx.x;
    const int wid  = tid >> 5;
    const int lane = tid & 31;
    const int ng   = blockIdx.x;          // 0..31 channel tile (16 ch)
    const int mg   = blockIdx.y;          // 0..3  row group (64 rows)
    const int m0   = mg << 6;
    const int ch0  = ng << 4;
    const int mt   = wid & 3;             // m16 tile
    const int nh   = wid >> 2;            // channel half (8 ch)

    // ---- prologue: Wh -> smem BT[n][k] fp16, n = chl*4 + gate ----
    {
        const int n   = tid >> 2;                 // 0..63
        const int kq  = (tid & 3) * 128;
        const int chl = n >> 2;
        const int gt  = n & 3;
        const float* wp = &Wh[(size_t)kq * G4 + gt * HH + ch0 + chl];
        char* bh = smc + SM_B + n * BPITCH + kq * 2;
        for (int k = 0; k < 128; ++k)
            *(__half*)(bh + k * 2) = __float2half(wp[(size_t)k * G4]);
    }
    __syncthreads();

    // ldsm addresses
    const int a_row = mt * 16 + (lane & 7) + ((lane >> 3) & 1) * 8;
    const uint32_t aH = sb + SM_A + a_row * APITCH + ((lane >> 4) & 1) * 16;
    const int b_row = (lane & 7) + ((lane >> 4) & 1) * 8;
    const uint32_t bH = sb + SM_B + (nh * 32 + b_row) * BPITCH + ((lane >> 3) & 1) * 16;

    // A staging: thread -> (row, k-seg of 64 fp16)
    const int sr   = tid >> 2;            // 0..63
    const int kseg = tid & 3;             // 0..3

    // epilogue mapping
    const int gr = lane >> 2;
    const int tc = lane & 3;
    const int row = m0 + mt * 16 + gr + (tc & 1) * 8;

    float cs[4], hs[4];
#pragma unroll
    for (int j = 0; j < 4; ++j) { cs[j] = 0.f; hs[j] = 0.f; }

    unsigned* bar = &g_bar4[mg];
    uint4 pf[8];

    for (int t = 0; t < TT; ++t) {
        const int hb = t & 1;

        // prefetch xw + kg for this step (latency hides under MMA chunks)
        float4 xw_r[4];
        float  kg_r[4];
#pragma unroll
        for (int dq = 0; dq < 4; ++dq) {
            const int ch = ch0 + nh * 8 + dq * 2 + (tc >> 1);
            xw_r[dq] = *(const float4*)&g_xw[((size_t)t * BB + row) * G4 + ch * 4];
            kg_r[dq] = g_kg[t * HH + ch];
        }

        float d[4][4];
#pragma unroll
        for (int j = 0; j < 4; ++j)
#pragma unroll
            for (int q = 0; q < 4; ++q) d[j][q] = 0.f;

        // stage chunk 0 (k 0..255)
        {
            const __half* hp = &g_hh[hb][m0 + sr][kseg * 64];
#pragma unroll
            for (int j = 0; j < 8; ++j) pf[j] = ((const uint4*)hp)[j];
            char* dst = smc + SM_A + sr * APITCH + kseg * 128;
#pragma unroll
            for (int j = 0; j < 8; ++j) *(uint4*)(dst + j * 16) = pf[j];
        }
        __syncthreads();

        for (int c = 0; c < 2; ++c) {
            const int buf = c;
            if (c == 0) {
                const __half* hp = &g_hh[hb][m0 + sr][256 + kseg * 64];
#pragma unroll
                for (int j = 0; j < 8; ++j) pf[j] = ((const uint4*)hp)[j];
            }

            // MMA over this 256-K chunk: 16 k16 steps
#pragma unroll
            for (int ks = 0; ks < 16; ++ks) {
                unsigned ah4[4];
                ldsm4(ah4, aH + buf * ABUF + ks * 32);
#pragma unroll
                for (int np2 = 0; np2 < 2; ++np2) {
                    unsigned bh4[4];
                    uint32_t bo = (uint32_t)(np2 * 16640 + c * 512 + ks * 32);
                    ldsm4(bh4, bH + bo);
                    mma_fp16(d[np2 * 2],     ah4, bh4 + 0);
                    mma_fp16(d[np2 * 2 + 1], ah4, bh4 + 2);
                }
            }

            if (c == 0) {
                char* dst = smc + SM_A + ABUF + sr * APITCH + kseg * 128;
#pragma unroll
                for (int j = 0; j < 8; ++j) *(uint4*)(dst + j * 16) = pf[j];
                __syncthreads();
            }
        }

        // ---- fused epilogue: gate regroup (shfl), gates, time gate, update ----
        const int nb = (t + 1) & 1;
#pragma unroll
        for (int dq = 0; dq < 4; ++dq) {
            float s0 = __shfl_xor_sync(0xffffffffu, (tc & 1) ? d[dq][0] : d[dq][2], 1);
            float s1 = __shfl_xor_sync(0xffffffffu, (tc & 1) ? d[dq][1] : d[dq][3], 1);
            float gi, gf, gg, go;
            if (tc & 1) { gi = s0;       gf = s1;       gg = d[dq][2]; go = d[dq][3]; }
            else        { gi = d[dq][0]; gf = d[dq][1]; gg = s0;       go = s1; }
            const int ch = ch0 + nh * 8 + dq * 2 + (tc >> 1);
            float4 xw = xw_r[dq];
            float kg = kg_r[dq];
            gi += xw.x; gf += xw.y; gg += xw.z; go += xw.w;
            gi = 1.0f / (1.0f + __expf(-gi));
            gf = 1.0f / (1.0f + __expf(-gf));
            gg = tanhf(gg);
            go = 1.0f / (1.0f + __expf(-go));
            float ct = gf * cs[dq] + gi * gg;
            float ht = go * tanhf(ct);
            cs[dq] = kg * ct + (1.0f - kg) * cs[dq];
            float hn = kg * ht + (1.0f - kg) * hs[dq];
            hs[dq] = hn;
            g_hh[nb][row][ch] = __float2half(hn);
            if (t == TT - 1) g_h[(size_t)row * HH + ch] = hn;
        }
        __syncthreads();

        // ---- per-m-group grid barrier over 32 blocks ----
        if (t < TT - 1) {
            if (tid == 0) {
                __threadfence();
                atomicAdd(bar, 1u);
                const unsigned tgt = (unsigned)(t + 1) * 32u;
                unsigned v;
                do {
                    asm volatile("ld.acquire.gpu.global.u32 %0, [%1];"
                                 : "=r"(v) : "l"(bar) : "memory");
                } while (v < tgt);
            }
            __syncthreads();
        }
    }
}

// ---------------------------------------------------------------------------
// Phase 3: head (logits + log_softmax)
// ---------------------------------------------------------------------------
__global__ void head_kernel(const float* __restrict__ fc_w,
                            const float* __restrict__ fc_b,
                            float* __restrict__ out) {
    __shared__ float hrow[HH];
    __shared__ float part[CC][4];
    __shared__ float logits[CC];
    __shared__ float s_lse;
    const int b = blockIdx.x;
    const int tid = threadIdx.x;   // 256

    *(float2*)&hrow[tid * 2] = *(const float2*)&g_h[(size_t)b * HH + tid * 2];
    __syncthreads();

    const int c = tid >> 2;
    const int s = tid & 3;
    if (c < CC) {
        float sum = 0.0f;
        const float* wp = &fc_w[(size_t)(s * 128) * CC + c];
        const float* hp = &hrow[s * 128];
#pragma unroll 16
        for (int k = 0; k < 128; ++k) sum += hp[k] * wp[k * CC];
        part[c][s] = sum;
    }
    __syncthreads();

    if (tid < CC)
        logits[tid] = part[tid][0] + part[tid][1] + part[tid][2] + part[tid][3] + fc_b[tid];
    __syncthreads();

    if (tid == 0) {
        float mx = -1e30f;
        for (int i = 0; i < CC; ++i) mx = fmaxf(mx, logits[i]);
        float sm = 0.0f;
        for (int i = 0; i < CC; ++i) sm += expf(logits[i] - mx);
        s_lse = mx + logf(sm);
    }
    __syncthreads();

    if (tid < CC) out[(size_t)b * CC + tid] = logits[tid] - s_lse;
}

// ---------------------------------------------------------------------------
// Launch
// ---------------------------------------------------------------------------
extern "C" void kernel_launch(void* const* d_in, const int* in_sizes, int n_in,
                              void* d_out, int out_size) {
    const float* x     = (const float*)d_in[0];
    const float* Wx    = (const float*)d_in[1];
    const float* Wh    = (const float*)d_in[2];
    const float* bias  = (const float*)d_in[3];
    const float* tau   = (const float*)d_in[4];
    const float* shift = (const float*)d_in[5];
    const float* fc_w  = (const float*)d_in[6];
    const float* fc_b  = (const float*)d_in[7];
    float* out = (float*)d_out;

    cudaFuncSetAttribute(xw_mma,
                         cudaFuncAttributeMaxDynamicSharedMemorySize, XSM_TOT);
    cudaFuncSetAttribute(plstm_mma,
                         cudaFuncAttributeMaxDynamicSharedMemorySize, SMEM_TOTAL);

    zero_state<<<512, 256>>>();
    kg_kernel<<<512, 256>>>(tau, shift);
    xprep<<<(int)(((size_t)MM * 160 + 255) / 256), 256>>>(x);
    wprep<<<(G4 * 160 + 255) / 256, 256>>>(Wx, bias);

    dim3 g1(G4 / 128, MM / 128);          // (16, 512)
    xw_mma<<<g1, 256, XSM_TOT>>>(0);

    dim3 g2(32, 4);                        // 128 persistent blocks
    plstm_mma<<<g2, 256, SMEM_TOTAL>>>(Wh);

    head_kernel<<<BB, 256>>>(fc_w, fc_b, out);
}

// round 16
// speedup vs baseline: 4.4510x; 1.1264x over previous
#include <cuda_runtime.h>
#include <cuda_fp16.h>
#include <math.h>
#include <stdint.h>

// Problem constants
#define BB 256
#define PP 5
#define TT 256
#define FF 128
#define HH 512
#define CC 60
#define DD 640      // P*F
#define G4 2048     // 4*H
#define MM 65536    // T*B rows

// Scratch (device globals: allocation-free per harness rules)
__device__ float g_xw[134217728ULL];           // (T*B) x [ch*4+gate] fp32
__device__ __half g_xh[(size_t)MM * DD];       // x fp16, [m][k]
__device__ __half g_wh[(size_t)G4 * DD];       // Wx fp16, [n'][k], n'=ch*4+gate
__device__ float g_bp[G4];                     // permuted bias
__device__ float g_h[BB * HH];                 // final h fp32 (for head)
__device__ __half g_hh[2][BB][HH];             // [buf][row][ch] fp16 h
__device__ float g_kg[TT * HH];                // time gate k(t,ch)
__device__ unsigned g_bar8[8];                 // per-m-group barrier counters

// ---------------------------------------------------------------------------
// MMA helpers (HMMA SASS; fragment patterns proven in R12-R15)
// ---------------------------------------------------------------------------
__device__ __forceinline__ void ldsm4(unsigned* r, uint32_t addr) {
    asm volatile("ldmatrix.sync.aligned.m8n8.x4.shared.b16 {%0, %1, %2, %3}, [%4];"
                 : "=r"(r[0]), "=r"(r[1]), "=r"(r[2]), "=r"(r[3]) : "r"(addr));
}

__device__ __forceinline__ void mma_fp16(float* d, const unsigned* a, const unsigned* b) {
    asm volatile(
        "mma.sync.aligned.m16n8k16.row.col.f32.f16.f16.f32 "
        "{%0, %1, %2, %3}, {%4, %5, %6, %7}, {%8, %9}, {%0, %1, %2, %3};"
        : "+f"(d[0]), "+f"(d[1]), "+f"(d[2]), "+f"(d[3])
        : "r"(a[0]), "r"(a[1]), "r"(a[2]), "r"(a[3]), "r"(b[0]), "r"(b[1]));
}

// ---------------------------------------------------------------------------
// Init / prep kernels
// ---------------------------------------------------------------------------
__global__ void zero_state() {
    int i = blockIdx.x * blockDim.x + threadIdx.x;
    if (i < 65536) ((float*)g_hh)[i] = 0.0f;   // zero g_hh[0] (256*512 fp16)
    if (i < 8) g_bar8[i] = 0u;
}

__global__ void kg_kernel(const float* __restrict__ tau,
                          const float* __restrict__ shift) {
    int i = blockIdx.x * blockDim.x + threadIdx.x;
    if (i < TT * HH) {
        int t = i >> 9, ch = i & 511;
        float tv = tau[ch], sv = shift[ch];
        float xph = ((float)t - sv) / tv;
        float phi = xph - floorf(xph);
        float kg = (phi < 0.025f) ? (40.0f * phi)
                 : (phi < 0.05f)  ? (2.0f - 40.0f * phi)
                                  : (0.001f * phi);
        g_kg[i] = kg;
    }
}

// X (B,P,T,F) fp32 -> g_xh [m][k] fp16, m = t*256+b, k = p*128+f
__global__ void xprep(const float* __restrict__ X) {
    size_t idx = (size_t)blockIdx.x * blockDim.x + threadIdx.x;
    if (idx >= (size_t)MM * 160) return;
    int m  = (int)(idx / 160);
    int kq = (int)(idx % 160) * 4;
    int t = m >> 8, b = m & 255;
    int p = kq >> 7, f = kq & 127;
    float4 v = *(const float4*)&X[(((size_t)b * PP + p) * TT + t) * FF + f];
    __half h4[4] = {__float2half(v.x), __float2half(v.y),
                    __float2half(v.z), __float2half(v.w)};
    *(uint2*)&g_xh[(size_t)m * DD + kq] = *(uint2*)h4;
}

// Wx [k][4H] fp32 -> g_wh [n'][k] fp16, n' = ch*4 + gate (wcol = gate*512+ch)
__global__ void wprep(const float* __restrict__ Wx, const float* __restrict__ bvec) {
    int idx = blockIdx.x * blockDim.x + threadIdx.x;
    if (idx >= G4 * 160) return;
    int np = idx / 160;
    int kq = (idx % 160) * 4;
    int gate = np & 3, ch = np >> 2;
    int wcol = gate * HH + ch;
    __half h4[4];
#pragma unroll
    for (int j = 0; j < 4; ++j)
        h4[j] = __float2half(Wx[(size_t)(kq + j) * G4 + wcol]);
    *(uint2*)&g_wh[(size_t)np * DD + kq] = *(uint2*)h4;
    if (kq == 0) g_bp[np] = bvec[wcol];
}

// ---------------------------------------------------------------------------
// Phase 1: XW GEMM on mma.sync, single fp16 product (unchanged from R15).
// ---------------------------------------------------------------------------
#define XSM_A 0          // A: [buf][128 rows][48B]
#define XSM_B 12288      // B: [buf][128 rows][48B]
#define XSM_TOT 24576

__global__ void __launch_bounds__(256, 2)
xw_mma(int dummy) {
    extern __shared__ char smc[];
    const uint32_t sb = (uint32_t)__cvta_generic_to_shared(smc);
    const int tid  = threadIdx.x;
    const int wid  = tid >> 5;
    const int lane = tid & 31;
    const int n0   = blockIdx.x << 7;
    const int m0   = blockIdx.y << 7;
    const int mw   = wid & 3;
    const int nw   = wid >> 2;

    const int a_row = mw * 32 + (lane & 7) + ((lane >> 3) & 1) * 8;
    const uint32_t aOff = sb + XSM_A + a_row * 48 + ((lane >> 4) & 1) * 16;
    const int b_row = (lane & 7) + ((lane >> 4) & 1) * 8;
    const uint32_t bOff = sb + XSM_B + (nw * 64 + b_row) * 48 + ((lane >> 3) & 1) * 16;

    const int arow = tid >> 1;
    const int ahf  = tid & 1;

    float d[2][8][4];
#pragma unroll
    for (int i = 0; i < 2; ++i)
#pragma unroll
        for (int j = 0; j < 8; ++j)
#pragma unroll
            for (int q = 0; q < 4; ++q) d[i][j][q] = 0.f;

    uint4 pa, pb;
    auto ldg = [&](int k0) {
        pa = *(const uint4*)&g_xh[(size_t)(m0 + arow) * DD + k0 + ahf * 8];
        pb = *(const uint4*)&g_wh[(size_t)(n0 + arow) * DD + k0 + ahf * 8];
    };
    auto sts = [&](int buf) {
        *(uint4*)(smc + XSM_A + buf * 6144 + arow * 48 + ahf * 16) = pa;
        *(uint4*)(smc + XSM_B + buf * 6144 + arow * 48 + ahf * 16) = pb;
    };

    ldg(0);
    sts(0);
    __syncthreads();

    for (int s = 0; s < 40; ++s) {
        const int buf = s & 1;
        if (s < 39) ldg((s + 1) * 16);

        unsigned bq[4][4];
#pragma unroll
        for (int p4 = 0; p4 < 4; ++p4)
            ldsm4(bq[p4], bOff + buf * 6144 + p4 * 16 * 48);
#pragma unroll
        for (int mt = 0; mt < 2; ++mt) {
            unsigned ah[4];
            ldsm4(ah, aOff + buf * 6144 + mt * 16 * 48);
#pragma unroll
            for (int p4 = 0; p4 < 4; ++p4) {
                mma_fp16(d[mt][2 * p4],     ah, bq[p4] + 0);
                mma_fp16(d[mt][2 * p4 + 1], ah, bq[p4] + 2);
            }
        }
        if (s < 39) sts(buf ^ 1);
        __syncthreads();
    }

    const int gr = lane >> 2;
    const int tc = lane & 3;
#pragma unroll
    for (int mt = 0; mt < 2; ++mt) {
        const int r0 = m0 + mw * 32 + mt * 16 + gr;
#pragma unroll
        for (int n8 = 0; n8 < 8; ++n8) {
            const int col = n0 + nw * 64 + n8 * 8 + tc * 2;
            float2 bs = *(const float2*)&g_bp[col];
            *(float2*)&g_xw[(size_t)r0 * G4 + col] =
                make_float2(d[mt][n8][0] + bs.x, d[mt][n8][1] + bs.y);
            *(float2*)&g_xw[(size_t)(r0 + 8) * G4 + col] =
                make_float2(d[mt][n8][2] + bs.x, d[mt][n8][3] + bs.y);
        }
    }
}

// ---------------------------------------------------------------------------
// Phase 2: PERSISTENT recurrence, retiled for minimal per-step choreography.
//   Grid (16, 8) = 128 blocks, 256 threads (8 warps).
//   Block: M=32 rows x N=128 cols (32 ch x 4 gates, n = chl*4+gate), K=512.
//   Warp (mt = wid&1 -> m16, nq = wid>>1 -> n32 = 8 channels).
//   Wh slice (128KB) resident; A (32 rows x 512 k = 32KB) staged ONCE per
//   step, single buffer, ONE syncthreads. Barrier domain = 16 blocks,
//   all-thread acquire-spin release.
// ---------------------------------------------------------------------------
#define RPITCH 1040                      // bytes per smem row (512 fp16 + pad)
#define SM_B   0                         // 128 rows
#define SM_A   133120                    // 32 rows
#define SMEM_TOTAL 166400

__global__ void __launch_bounds__(256, 1)
plstm_mma(const float* __restrict__ Wh) {
    extern __shared__ char smc[];
    const uint32_t sb = (uint32_t)__cvta_generic_to_shared(smc);
    const int tid  = threadIdx.x;
    const int wid  = tid >> 5;
    const int lane = tid & 31;
    const int ch0  = blockIdx.x << 5;     // 16 ch-tiles of 32 channels
    const int mg   = blockIdx.y;          // 0..7 row group (32 rows)
    const int m0   = mg << 5;
    const int mt   = wid & 1;             // m16 tile
    const int nq   = wid >> 1;            // n32 slice (8 channels)

    // ---- prologue: Wh -> smem BT[n][k] fp16, n = chl*4 + gate ----
    {
        const int chl = tid & 31;
        const int gt  = (tid >> 5) & 3;
        const int kh  = tid >> 7;                 // 0/1
        const float* wp = &Wh[(size_t)(kh * 256) * G4 + gt * HH + ch0 + chl];
        char* bh = smc + SM_B + (chl * 4 + gt) * RPITCH + kh * 512;
        for (int k = 0; k < 256; ++k)
            *(__half*)(bh + k * 2) = __float2half(wp[(size_t)k * G4]);
    }

    // ldsm addresses
    const int a_row = mt * 16 + (lane & 7) + ((lane >> 3) & 1) * 8;
    const uint32_t aH = sb + SM_A + a_row * RPITCH + ((lane >> 4) & 1) * 16;
    const int b_row = (lane & 7) + ((lane >> 4) & 1) * 8;
    const uint32_t bH = sb + SM_B + (nq * 32 + b_row) * RPITCH + ((lane >> 3) & 1) * 16;

    // A staging: thread -> (row sr, k-seg of 64 fp16)
    const int sr   = tid >> 3;            // 0..31
    const int kseg = tid & 7;             // 0..7

    // epilogue mapping
    const int gr = lane >> 2;
    const int tc = lane & 3;
    const int row = m0 + mt * 16 + gr + (tc & 1) * 8;

    float cs[4], hs[4];
#pragma unroll
    for (int j = 0; j < 4; ++j) { cs[j] = 0.f; hs[j] = 0.f; }

    unsigned* bar = &g_bar8[mg];
    __syncthreads();   // B ready

    for (int t = 0; t < TT; ++t) {
        const int hb = t & 1;

        // prefetch xw + kg for this step (hidden under staging + MMA)
        float4 xw_r[4];
        float  kg_r[4];
#pragma unroll
        for (int dq = 0; dq < 4; ++dq) {
            const int ch = ch0 + nq * 8 + dq * 2 + (tc >> 1);
            xw_r[dq] = *(const float4*)&g_xw[((size_t)t * BB + row) * G4 + ch * 4];
            kg_r[dq] = g_kg[t * HH + ch];
        }

        // ---- stage A: whole K=512 (32 rows), one buffer, one sync ----
        {
            const __half* hp = &g_hh[hb][m0 + sr][kseg * 64];
            uint4 v[8];
#pragma unroll
            for (int j = 0; j < 8; ++j) v[j] = ((const uint4*)hp)[j];
            char* dst = smc + SM_A + sr * RPITCH + kseg * 128;
#pragma unroll
            for (int j = 0; j < 8; ++j) *(uint4*)(dst + j * 16) = v[j];
        }
        __syncthreads();

        // ---- MMA: m16n32k512 per warp = 32 ksteps x 4 MMAs ----
        float d[4][4];
#pragma unroll
        for (int j = 0; j < 4; ++j)
#pragma unroll
            for (int q = 0; q < 4; ++q) d[j][q] = 0.f;

#pragma unroll
        for (int ks = 0; ks < 32; ++ks) {
            unsigned ah4[4];
            ldsm4(ah4, aH + ks * 32);
#pragma unroll
            for (int np2 = 0; np2 < 2; ++np2) {
                unsigned bh4[4];
                ldsm4(bh4, bH + (uint32_t)(np2 * 16 * RPITCH + ks * 32));
                mma_fp16(d[np2 * 2],     ah4, bh4 + 0);
                mma_fp16(d[np2 * 2 + 1], ah4, bh4 + 2);
            }
        }

        // ---- fused epilogue: gate regroup (shfl), gates, time gate, update ----
        const int nb = (t + 1) & 1;
#pragma unroll
        for (int dq = 0; dq < 4; ++dq) {
            float s0 = __shfl_xor_sync(0xffffffffu, (tc & 1) ? d[dq][0] : d[dq][2], 1);
            float s1 = __shfl_xor_sync(0xffffffffu, (tc & 1) ? d[dq][1] : d[dq][3], 1);
            float gi, gf, gg, go;
            if (tc & 1) { gi = s0;       gf = s1;       gg = d[dq][2]; go = d[dq][3]; }
            else        { gi = d[dq][0]; gf = d[dq][1]; gg = s0;       go = s1; }
            const int ch = ch0 + nq * 8 + dq * 2 + (tc >> 1);
            float4 xw = xw_r[dq];
            float kg = kg_r[dq];
            gi += xw.x; gf += xw.y; gg += xw.z; go += xw.w;
            gi = 1.0f / (1.0f + __expf(-gi));
            gf = 1.0f / (1.0f + __expf(-gf));
            gg = tanhf(gg);
            go = 1.0f / (1.0f + __expf(-go));
            float ct = gf * cs[dq] + gi * gg;
            float ht = go * tanhf(ct);
            cs[dq] = kg * ct + (1.0f - kg) * cs[dq];
            float hn = kg * ht + (1.0f - kg) * hs[dq];
            hs[dq] = hn;
            g_hh[nb][row][ch] = __float2half(hn);
            if (t == TT - 1) g_h[(size_t)row * HH + ch] = hn;
        }

        // ---- per-m-group barrier over 16 blocks, all-thread spin ----
        if (t < TT - 1) {
            __syncthreads();             // block arrival (also guards SM_A reuse)
            if (tid == 0) {
                __threadfence();
                atomicAdd(bar, 1u);
            }
            const unsigned tgt = (unsigned)(t + 1) * 16u;
            unsigned v;
            do {
                asm volatile("ld.acquire.gpu.global.u32 %0, [%1];"
                             : "=r"(v) : "l"(bar) : "memory");
            } while (v < tgt);
        }
    }
}

// ---------------------------------------------------------------------------
// Phase 3: head (logits + log_softmax)
// ---------------------------------------------------------------------------
__global__ void head_kernel(const float* __restrict__ fc_w,
                            const float* __restrict__ fc_b,
                            float* __restrict__ out) {
    __shared__ float hrow[HH];
    __shared__ float part[CC][4];
    __shared__ float logits[CC];
    __shared__ float s_lse;
    const int b = blockIdx.x;
    const int tid = threadIdx.x;   // 256

    *(float2*)&hrow[tid * 2] = *(const float2*)&g_h[(size_t)b * HH + tid * 2];
    __syncthreads();

    const int c = tid >> 2;
    const int s = tid & 3;
    if (c < CC) {
        float sum = 0.0f;
        const float* wp = &fc_w[(size_t)(s * 128) * CC + c];
        const float* hp = &hrow[s * 128];
#pragma unroll 16
        for (int k = 0; k < 128; ++k) sum += hp[k] * wp[k * CC];
        part[c][s] = sum;
    }
    __syncthreads();

    if (tid < CC)
        logits[tid] = part[tid][0] + part[tid][1] + part[tid][2] + part[tid][3] + fc_b[tid];
    __syncthreads();

    if (tid == 0) {
        float mx = -1e30f;
        for (int i = 0; i < CC; ++i) mx = fmaxf(mx, logits[i]);
        float sm = 0.0f;
        for (int i = 0; i < CC; ++i) sm += expf(logits[i] - mx);
        s_lse = mx + logf(sm);
    }
    __syncthreads();

    if (tid < CC) out[(size_t)b * CC + tid] = logits[tid] - s_lse;
}

// ---------------------------------------------------------------------------
// Launch
// ---------------------------------------------------------------------------
extern "C" void kernel_launch(void* const* d_in, const int* in_sizes, int n_in,
                              void* d_out, int out_size) {
    const float* x     = (const float*)d_in[0];
    const float* Wx    = (const float*)d_in[1];
    const float* Wh    = (const float*)d_in[2];
    const float* bias  = (const float*)d_in[3];
    const float* tau   = (const float*)d_in[4];
    const float* shift = (const float*)d_in[5];
    const float* fc_w  = (const float*)d_in[6];
    const float* fc_b  = (const float*)d_in[7];
    float* out = (float*)d_out;

    cudaFuncSetAttribute(xw_mma,
                         cudaFuncAttributeMaxDynamicSharedMemorySize, XSM_TOT);
    cudaFuncSetAttribute(plstm_mma,
                         cudaFuncAttributeMaxDynamicSharedMemorySize, SMEM_TOTAL);

    zero_state<<<512, 256>>>();
    kg_kernel<<<512, 256>>>(tau, shift);
    xprep<<<(int)(((size_t)MM * 160 + 255) / 256), 256>>>(x);
    wprep<<<(G4 * 160 + 255) / 256, 256>>>(Wx, bias);

    dim3 g1(G4 / 128, MM / 128);          // (16, 512)
    xw_mma<<<g1, 256, XSM_TOT>>>(0);

    dim3 g2(16, 8);                        // 128 persistent blocks
    plstm_mma<<<g2, 256, SMEM_TOTAL>>>(Wh);

    head_kernel<<<BB, 256>>>(fc_w, fc_b, out);
}